// round 14
// baseline (speedup 1.0000x reference)
#include <cuda_runtime.h>
#include <cuda_bf16.h>
#include <cuda_fp16.h>
#include <math.h>
#include <stdint.h>

// ---------------- problem constants ----------------
#define TOK    2048
#define DMODEL 1024
#define DQKV   3072
#define DFF    4096
#define NL     8

// ---------------- scratch (device globals, no allocs) ----------------
__device__ float g_x[TOK * DMODEL];

__device__ __half a_xA[TOK * DMODEL];
__device__ __half a_xB[TOK * DMODEL];
__device__ __half s_v2[TOK * DMODEL];
__device__ __half s_v3[TOK * DMODEL];
__device__ __half s_v4[TOK * DMODEL];
__device__ __half a_qkv_h[TOK * DQKV];
__device__ __half a_qkv_l[TOK * DQKV];
__device__ __half a_at[TOK * DMODEL];
__device__ __half a_ln[TOK * DMODEL];
__device__ __half a_ff[TOK * DFF];
__device__ __half w_qkv[NL * DQKV * DMODEL];
__device__ __half w_ao [NL * DMODEL * DMODEL];
__device__ __half w_mi [NL * DFF * DMODEL];
__device__ __half w_mo [NL * DMODEL * DFF];
__device__ __half w_sk [4 * DMODEL * 2 * DMODEL];  // cols >=1024 pre-scaled by 2^-0.5

// ---------------- helpers ----------------
__device__ __forceinline__ uint32_t smem_u32(const void* p) {
    uint32_t a;
    asm("{ .reg .u64 t; cvta.to.shared.u64 t, %1; cvt.u32.u64 %0, t; }"
        : "=r"(a) : "l"(p));
    return a;
}

__device__ __forceinline__ void cp16(uint32_t dst, const void* src) {
    asm volatile("cp.async.cg.shared.global [%0], [%1], 16;" :: "r"(dst), "l"(src));
}

__device__ __forceinline__ void ldm_x4(uint32_t addr, uint32_t& r0, uint32_t& r1,
                                       uint32_t& r2, uint32_t& r3) {
    asm volatile("ldmatrix.sync.aligned.m8n8.x4.shared.b16 {%0,%1,%2,%3}, [%4];"
                 : "=r"(r0), "=r"(r1), "=r"(r2), "=r"(r3) : "r"(addr));
}

__device__ __forceinline__ void ldm_x4t(uint32_t addr, uint32_t& r0, uint32_t& r1,
                                        uint32_t& r2, uint32_t& r3) {
    asm volatile("ldmatrix.sync.aligned.m8n8.x4.trans.shared.b16 {%0,%1,%2,%3}, [%4];"
                 : "=r"(r0), "=r"(r1), "=r"(r2), "=r"(r3) : "r"(addr));
}

__device__ __forceinline__ void mma_fp(float* c, const uint32_t* a,
                                       uint32_t b0, uint32_t b1) {
    asm volatile(
        "mma.sync.aligned.m16n8k16.row.col.f32.f16.f16.f32 "
        "{%0,%1,%2,%3}, {%4,%5,%6,%7}, {%8,%9}, {%0,%1,%2,%3};"
        : "+f"(c[0]), "+f"(c[1]), "+f"(c[2]), "+f"(c[3])
        : "r"(a[0]), "r"(a[1]), "r"(a[2]), "r"(a[3]), "r"(b0), "r"(b1));
}

__device__ __forceinline__ void split_h(float v, uint16_t& h, uint16_t& l) {
    __half hb = __float2half_rn(v);
    __half lb = __float2half_rn(v - __half2float(hb));
    h = *(uint16_t*)&hb;
    l = *(uint16_t*)&lb;
}

// ---------------- single-fp16 HMMA GEMM ----------------
// C = act(A * W^T + bias)(+res); A, W single fp16.
// FM=4 -> 128x128, FM=2 -> 64x128, FM=1 -> 32x128 CTA tile. NST=4 stages.
// MINB = min blocks/SM for launch_bounds.
// FLAGS: 1=bias, 2=gelu, 4=residual(fp32), 8=write fp16, 16=write fp32,
//        128=also write fp16 to Cb2, 256=write fp16 hi/lo (lo only c0<lo_limit)
#define GBK   32
#define GROWB 80
#define GNST  4

template<int FLAGS, bool SPLITA, int FM, int MINB>
__global__ void __launch_bounds__(256, MINB) gemm_f16(
    const __half* __restrict__ Ah, const __half* __restrict__ A2h,
    const __half* __restrict__ W,
    const float* __restrict__ bias, const float* __restrict__ res,
    float* __restrict__ C, uint16_t* __restrict__ Cb,
    uint16_t* __restrict__ Cph, uint16_t* __restrict__ Cpl,
    uint16_t* __restrict__ Cb2, int N, int K, int lo_limit)
{
    constexpr int BM     = FM * 32;
    constexpr int ATILEB = BM * GROWB;
    constexpr int WTILEB = 128 * GROWB;
    constexpr int STRIDE = ATILEB + WTILEB;

    extern __shared__ char smem[];
    const uint32_t sb = smem_u32(smem);
    const int tid  = threadIdx.x;
    const int wid  = tid >> 5;
    const int lane = tid & 31;
    const int wm   = wid >> 2;
    const int wn   = wid & 3;
    const int bm   = blockIdx.y * BM;
    const int bn   = blockIdx.x * 128;

    // A load mapping (per stage: BM rows x 64 B)
    const int a_r = (FM == 4) ? (tid >> 1) : (FM == 2) ? (tid >> 2) : (tid >> 2);
    const int a_c = (FM == 4) ? ((tid & 1) * 16)
                  : (FM == 2) ? ((tid & 3) * 8) : ((tid & 3) * 8);   // halfs
    const uint32_t sA = (uint32_t)a_r * GROWB + a_c * 2;
    const size_t a_goffK = (size_t)(bm + a_r) * K + a_c;
    const size_t a_goff1 = (size_t)(bm + a_r) * 1024 + a_c;
    // W load mapping
    const int w_r = tid >> 1;
    const int w_c = (tid & 1) * 16;
    const uint32_t sW = (uint32_t)(ATILEB) + (uint32_t)w_r * GROWB + w_c * 2;
    const size_t w_goff = (size_t)(bn + w_r) * K + w_c;

    auto load_stage = [&](int s) {
        const uint32_t base = sb + (uint32_t)(s & (GNST - 1)) * STRIDE;
        const size_t ko = (size_t)s * GBK;
        const __half* pa;
        if (SPLITA) {
            pa = (ko >= 1024) ? (A2h + a_goff1 + (ko - 1024)) : (Ah + a_goff1 + ko);
        } else {
            pa = Ah + a_goffK + ko;
        }
        if (FM == 4) {
            cp16(base + sA,      pa);
            cp16(base + sA + 16, pa + 8);
        } else if (FM == 2) {
            cp16(base + sA, pa);
        } else {                          // FM == 1: only 128 threads load A
            if (tid < 128) cp16(base + sA, pa);
        }
        const __half* pw = W + w_goff + ko;
        cp16(base + sW,      pw);
        cp16(base + sW + 16, pw + 8);
        asm volatile("cp.async.commit_group;");
    };

    const int S = K / GBK;
    for (int s = 0; s < GNST - 1; s++) load_stage(s);

    float acc[FM][4][4];
#pragma unroll
    for (int i = 0; i < FM; i++)
#pragma unroll
        for (int j = 0; j < 4; j++)
#pragma unroll
            for (int k = 0; k < 4; k++) acc[i][j][k] = 0.f;

    const uint32_t aoff = (uint32_t)(wm * (FM * 16) + (lane & 15)) * GROWB
                        + (lane >> 4) * 16;
    const uint32_t boff = (uint32_t)(wn * 32 + (lane & 7) + ((lane >> 4) & 1) * 8) * GROWB
                        + ((lane >> 3) & 1) * 16 + ATILEB;

    for (int s = 0; s < S; s++) {
        asm volatile("cp.async.wait_group %0;" :: "n"(GNST - 2) : "memory");
        __syncthreads();

        const int pf = s + GNST - 1;
        if (pf < S) load_stage(pf);
        else        asm volatile("cp.async.commit_group;");

        const uint32_t base = sb + (uint32_t)(s & (GNST - 1)) * STRIDE;
        if (FM == 2) {
            // stage-wide LDSM hoist
            uint32_t ah[2][2][4], bb[2][2][4];
#pragma unroll
            for (int k16 = 0; k16 < 2; k16++) {
#pragma unroll
                for (int fm = 0; fm < 2; fm++) {
                    const uint32_t ao = base + aoff + fm * 16 * GROWB + k16 * 32;
                    ldm_x4(ao, ah[k16][fm][0], ah[k16][fm][1],
                               ah[k16][fm][2], ah[k16][fm][3]);
                }
#pragma unroll
                for (int fnp = 0; fnp < 2; fnp++) {
                    const uint32_t bo = base + boff + fnp * 16 * GROWB + k16 * 32;
                    ldm_x4(bo, bb[k16][fnp][0], bb[k16][fnp][1],
                               bb[k16][fnp][2], bb[k16][fnp][3]);
                }
            }
#pragma unroll
            for (int k16 = 0; k16 < 2; k16++)
#pragma unroll
                for (int fm = 0; fm < 2; fm++)
#pragma unroll
                    for (int fnp = 0; fnp < 2; fnp++) {
                        mma_fp(acc[fm][fnp * 2 + 0], ah[k16][fm],
                               bb[k16][fnp][0], bb[k16][fnp][1]);
                        mma_fp(acc[fm][fnp * 2 + 1], ah[k16][fm],
                               bb[k16][fnp][2], bb[k16][fnp][3]);
                    }
        } else {
#pragma unroll
            for (int k16 = 0; k16 < 2; k16++) {
                uint32_t ah[FM][4], bb[2][4];
#pragma unroll
                for (int fm = 0; fm < FM; fm++) {
                    const uint32_t ao = base + aoff + fm * 16 * GROWB + k16 * 32;
                    ldm_x4(ao, ah[fm][0], ah[fm][1], ah[fm][2], ah[fm][3]);
                }
#pragma unroll
                for (int fnp = 0; fnp < 2; fnp++) {
                    const uint32_t bo = base + boff + fnp * 16 * GROWB + k16 * 32;
                    ldm_x4(bo, bb[fnp][0], bb[fnp][1], bb[fnp][2], bb[fnp][3]);
                }
#pragma unroll
                for (int fm = 0; fm < FM; fm++) {
#pragma unroll
                    for (int fnp = 0; fnp < 2; fnp++) {
                        mma_fp(acc[fm][fnp * 2 + 0], ah[fm], bb[fnp][0], bb[fnp][1]);
                        mma_fp(acc[fm][fnp * 2 + 1], ah[fm], bb[fnp][2], bb[fnp][3]);
                    }
                }
            }
        }
    }

    // ---- epilogue ----
#pragma unroll
    for (int fm = 0; fm < FM; fm++) {
#pragma unroll
        for (int fn = 0; fn < 4; fn++) {
            const int r0 = bm + wm * (FM * 16) + fm * 16 + (lane >> 2);
            const int c0 = bn + wn * 32 + fn * 8 + (lane & 3) * 2;
            float v[4] = { acc[fm][fn][0], acc[fm][fn][1],
                           acc[fm][fn][2], acc[fm][fn][3] };
            if (FLAGS & 1) {
                const float b0 = __ldg(bias + c0), b1 = __ldg(bias + c0 + 1);
                v[0] += b0; v[1] += b1; v[2] += b0; v[3] += b1;
            }
            if (FLAGS & 2) {
#pragma unroll
                for (int u = 0; u < 4; u++)
                    v[u] = 0.5f * v[u] * (1.f + erff(v[u] * 0.7071067811865476f));
            }
            if (FLAGS & 4) {
                const float2 ra = *(const float2*)(res + (size_t)r0 * N + c0);
                const float2 rb = *(const float2*)(res + (size_t)(r0 + 8) * N + c0);
                v[0] += ra.x; v[1] += ra.y; v[2] += rb.x; v[3] += rb.y;
            }
            if (FLAGS & 16) {
                float2 oa; oa.x = v[0]; oa.y = v[1];
                float2 ob; ob.x = v[2]; ob.y = v[3];
                *(float2*)(C + (size_t)r0 * N + c0) = oa;
                *(float2*)(C + (size_t)(r0 + 8) * N + c0) = ob;
            }
            if (FLAGS & 8) {
#pragma unroll
                for (int hf = 0; hf < 2; hf++) {
                    const int rr = r0 + hf * 8;
                    __half2 p = __floats2half2_rn(v[hf * 2 + 0], v[hf * 2 + 1]);
                    *(uint32_t*)(Cb + (size_t)rr * N + c0) = *(uint32_t*)&p;
                    if (FLAGS & 128)
                        *(uint32_t*)(Cb2 + (size_t)rr * N + c0) = *(uint32_t*)&p;
                }
            }
            if (FLAGS & 256) {
                uint16_t h0, l0, h1, l1;
                const bool store_lo = c0 < lo_limit;
#pragma unroll
                for (int hf = 0; hf < 2; hf++) {
                    const int rr = r0 + hf * 8;
                    split_h(v[hf * 2 + 0], h0, l0);
                    split_h(v[hf * 2 + 1], h1, l1);
                    *(uint32_t*)(Cph + (size_t)rr * N + c0) = (uint32_t)h0 | ((uint32_t)h1 << 16);
                    if (store_lo)
                        *(uint32_t*)(Cpl + (size_t)rr * N + c0) = (uint32_t)l0 | ((uint32_t)l1 << 16);
                }
            }
        }
    }
}

// GEMM smem sizes (NST=4)
#define GSMEM_FM4 ((128 * GROWB + 128 * GROWB) * GNST)   // 81920
#define GSMEM_FM2 ((64 * GROWB + 128 * GROWB) * GNST)    // 61440
#define GSMEM_FM1 ((32 * GROWB + 128 * GROWB) * GNST)    // 51200

// ---------------- fp16 flash attention (QK 3-term, PV 2-term) ---------------
#define ASTR 144
#define ATB  (64 * ASTR)
#define ATTN_SMEM (8 * ATB)      // Qh,Ql + 2 x (Kh,Kl,Vh) = 73728 B

__global__ void __launch_bounds__(128) attn_hmma(
    const __half* __restrict__ qh, const __half* __restrict__ ql,
    uint16_t* __restrict__ out)
{
    extern __shared__ char smc[];
    const uint32_t sb = smem_u32(smc);
    const int b = blockIdx.z, h = blockIdx.y, q0 = blockIdx.x * 64;
    const int tid = threadIdx.x, wid = tid >> 5, lane = tid & 31;
    const float slope = -exp2f(-0.5f * (float)(h + 1));
    const size_t base = (size_t)b * 1024 * DQKV + (size_t)h * 64;

    {
        const int which = tid >> 6, r = tid & 63;
        const __half* src = (which ? ql : qh) + base + (size_t)(q0 + r) * DQKV;
        const uint32_t dst = sb + which * ATB + r * ASTR;
#pragma unroll
        for (int c = 0; c < 8; c++) cp16(dst + c * 16, src + c * 8);
        asm volatile("cp.async.commit_group;");
    }

    auto load_kv = [&](int t) {
        const uint32_t bufb = sb + 2 * ATB + (t & 1) * (3 * ATB);
        if (wid < 2) {
            const __half* sp = (wid ? ql : qh) + base + 1024;
#pragma unroll
            for (int rr = 0; rr < 2; rr++) {
                const int r = lane + rr * 32;
                const __half* src = sp + (size_t)(t * 64 + r) * DQKV;
                const uint32_t dst = bufb + wid * ATB + r * ASTR;
#pragma unroll
                for (int c = 0; c < 8; c++) cp16(dst + c * 16, src + c * 8);
            }
        } else {
            const int r = (wid - 2) * 32 + lane;
            const __half* src = qh + base + 2048 + (size_t)(t * 64 + r) * DQKV;
            const uint32_t dst = bufb + 2 * ATB + r * ASTR;
#pragma unroll
            for (int c = 0; c < 8; c++) cp16(dst + c * 16, src + c * 8);
        }
        asm volatile("cp.async.commit_group;");
    };

    load_kv(0);
    asm volatile("cp.async.wait_group 0;" ::: "memory");
    __syncthreads();

    uint32_t qfh[4][4], qfl[4][4];
    {
        const uint32_t ao = sb + (uint32_t)(wid * 16 + (lane & 15)) * ASTR + (lane >> 4) * 16;
#pragma unroll
        for (int kk = 0; kk < 4; kk++) {
            ldm_x4(ao + kk * 32,       qfh[kk][0], qfh[kk][1], qfh[kk][2], qfh[kk][3]);
            ldm_x4(ao + ATB + kk * 32, qfl[kk][0], qfl[kk][1], qfl[kk][2], qfl[kk][3]);
        }
        const __half2 sc = __floats2half2_rn(0.125f, 0.125f);
#pragma unroll
        for (int kk = 0; kk < 4; kk++)
#pragma unroll
            for (int u = 0; u < 4; u++) {
                __half2 vh = *(__half2*)&qfh[kk][u];
                __half2 vl = *(__half2*)&qfl[kk][u];
                vh = __hmul2(vh, sc); vl = __hmul2(vl, sc);
                qfh[kk][u] = *(uint32_t*)&vh; qfl[kk][u] = *(uint32_t*)&vl;
            }
    }

    const int rA = q0 + wid * 16 + (lane >> 2);
    const int rB = rA + 8;
    const bool okA = rA < 1023, okB = rB < 1023;

    float m0 = -1e30f, m1 = -1e30f, l0s = 0.f, l1s = 0.f;
    float oacc[8][4];
#pragma unroll
    for (int j = 0; j < 8; j++)
#pragma unroll
        for (int u = 0; u < 4; u++) oacc[j][u] = 0.f;

    for (int t = 0; t < 16; t++) {
        if (t > 0) {
            asm volatile("cp.async.wait_group 0;" ::: "memory");
            __syncthreads();
        }
        if (t < 15) load_kv(t + 1);

        const uint32_t kb = sb + 2 * ATB + (t & 1) * (3 * ATB);
        const uint32_t vb = kb + 2 * ATB;

        float s[8][4];
#pragma unroll
        for (int j = 0; j < 8; j++)
#pragma unroll
            for (int u = 0; u < 4; u++) s[j][u] = 0.f;

        const uint32_t bbase = kb + (uint32_t)((lane & 7) + ((lane >> 4) & 1) * 8) * ASTR
                             + ((lane >> 3) & 1) * 16;
#pragma unroll
        for (int kk = 0; kk < 4; kk++) {
#pragma unroll
            for (int nb = 0; nb < 4; nb++) {
                uint32_t b0, b1, b2, b3, c0, c1, c2, c3;
                const uint32_t ad = bbase + nb * 16 * ASTR + kk * 32;
                ldm_x4(ad,       b0, b1, b2, b3);
                ldm_x4(ad + ATB, c0, c1, c2, c3);
                mma_fp(s[nb*2],   qfh[kk], b0, b1);
                mma_fp(s[nb*2],   qfl[kk], b0, b1);
                mma_fp(s[nb*2],   qfh[kk], c0, c1);
                mma_fp(s[nb*2+1], qfh[kk], b2, b3);
                mma_fp(s[nb*2+1], qfl[kk], b2, b3);
                mma_fp(s[nb*2+1], qfh[kk], c2, c3);
            }
        }

        float tmax0 = -1e30f, tmax1 = -1e30f;
#pragma unroll
        for (int j = 0; j < 8; j++) {
            const int kj = t * 64 + j * 8 + (lane & 3) * 2;
            const bool k0ok = kj < 1023, k1ok = kj + 1 < 1023;
            s[j][0] += (okA && k0ok) ? slope * fabsf((float)(rA - kj))     : 0.f;
            s[j][1] += (okA && k1ok) ? slope * fabsf((float)(rA - kj - 1)) : 0.f;
            s[j][2] += (okB && k0ok) ? slope * fabsf((float)(rB - kj))     : 0.f;
            s[j][3] += (okB && k1ok) ? slope * fabsf((float)(rB - kj - 1)) : 0.f;
            tmax0 = fmaxf(tmax0, fmaxf(s[j][0], s[j][1]));
            tmax1 = fmaxf(tmax1, fmaxf(s[j][2], s[j][3]));
        }
        tmax0 = fmaxf(tmax0, __shfl_xor_sync(0xffffffffu, tmax0, 1));
        tmax0 = fmaxf(tmax0, __shfl_xor_sync(0xffffffffu, tmax0, 2));
        tmax1 = fmaxf(tmax1, __shfl_xor_sync(0xffffffffu, tmax1, 1));
        tmax1 = fmaxf(tmax1, __shfl_xor_sync(0xffffffffu, tmax1, 2));

        const float mn0 = fmaxf(m0, tmax0), mn1 = fmaxf(m1, tmax1);
        const float al0 = __expf(m0 - mn0), al1 = __expf(m1 - mn1);
        m0 = mn0; m1 = mn1;

        float rs0 = 0.f, rs1 = 0.f;
#pragma unroll
        for (int j = 0; j < 8; j++) {
            s[j][0] = __expf(s[j][0] - mn0); rs0 += s[j][0];
            s[j][1] = __expf(s[j][1] - mn0); rs0 += s[j][1];
            s[j][2] = __expf(s[j][2] - mn1); rs1 += s[j][2];
            s[j][3] = __expf(s[j][3] - mn1); rs1 += s[j][3];
        }
        rs0 += __shfl_xor_sync(0xffffffffu, rs0, 1);
        rs0 += __shfl_xor_sync(0xffffffffu, rs0, 2);
        rs1 += __shfl_xor_sync(0xffffffffu, rs1, 1);
        rs1 += __shfl_xor_sync(0xffffffffu, rs1, 2);
        l0s = l0s * al0 + rs0;
        l1s = l1s * al1 + rs1;
#pragma unroll
        for (int j = 0; j < 8; j++) {
            oacc[j][0] *= al0; oacc[j][1] *= al0;
            oacc[j][2] *= al1; oacc[j][3] *= al1;
        }

        uint32_t pfh[4][4], pfl[4][4];
#pragma unroll
        for (int kk = 0; kk < 4; kk++) {
#pragma unroll
            for (int half = 0; half < 2; half++) {
                const int j = 2 * kk + half;
                uint16_t h0, l0, h1, l1, h2, l2, h3, l3;
                split_h(s[j][0], h0, l0); split_h(s[j][1], h1, l1);
                split_h(s[j][2], h2, l2); split_h(s[j][3], h3, l3);
                pfh[kk][half*2+0] = (uint32_t)h0 | ((uint32_t)h1 << 16);
                pfh[kk][half*2+1] = (uint32_t)h2 | ((uint32_t)h3 << 16);
                pfl[kk][half*2+0] = (uint32_t)l0 | ((uint32_t)l1 << 16);
                pfl[kk][half*2+1] = (uint32_t)l2 | ((uint32_t)l3 << 16);
            }
        }

        const uint32_t vbase = vb + (uint32_t)(((lane >> 3) & 1) * 8 + (lane & 7)) * ASTR
                             + (lane >> 4) * 16;
#pragma unroll
        for (int kk = 0; kk < 4; kk++) {
#pragma unroll
            for (int nb = 0; nb < 4; nb++) {
                uint32_t v0, v1, v2, v3;
                const uint32_t ad = vbase + kk * 16 * ASTR + nb * 32;
                ldm_x4t(ad, v0, v1, v2, v3);
                mma_fp(oacc[nb*2],   pfh[kk], v0, v1);
                mma_fp(oacc[nb*2],   pfl[kk], v0, v1);
                mma_fp(oacc[nb*2+1], pfh[kk], v2, v3);
                mma_fp(oacc[nb*2+1], pfl[kk], v2, v3);
            }
        }
    }

    const float inv0 = 1.f / l0s, inv1 = 1.f / l1s;
#pragma unroll
    for (int j = 0; j < 8; j++) {
        const int d0 = j * 8 + (lane & 3) * 2;
        size_t o = ((size_t)b * 1024 + rA) * DMODEL + h * 64 + d0;
        __half2 pa = __floats2half2_rn(oacc[j][0] * inv0, oacc[j][1] * inv0);
        *(uint32_t*)(out + o) = *(uint32_t*)&pa;
        o += (size_t)8 * DMODEL;
        __half2 pb = __floats2half2_rn(oacc[j][2] * inv1, oacc[j][3] * inv1);
        *(uint32_t*)(out + o) = *(uint32_t*)&pb;
    }
}

// ---------------- LayerNorm (warp-shuffle reduction) ----------------
template<bool HL>
__global__ void __launch_bounds__(256) ln_kernel2(
    const float* __restrict__ x, const float* __restrict__ g,
    float* __restrict__ y, uint16_t* __restrict__ yh)
{
    __shared__ float ws1[8], ws2[8];
    const int row = blockIdx.x;
    const int tid = threadIdx.x;
    const int wid = tid >> 5, lane = tid & 31;
    const float* xr = x + (size_t)row * DMODEL;

    float v[4];
    float s = 0.f;
#pragma unroll
    for (int u = 0; u < 4; u++) { v[u] = xr[tid + u * 256]; s += v[u]; }
#pragma unroll
    for (int o = 16; o; o >>= 1) s += __shfl_xor_sync(0xffffffffu, s, o);
    if (lane == 0) ws1[wid] = s;
    __syncthreads();
    float sum = 0.f;
#pragma unroll
    for (int w = 0; w < 8; w++) sum += ws1[w];
    const float mu = sum * (1.f / 1024.f);

    float q = 0.f;
#pragma unroll
    for (int u = 0; u < 4; u++) { const float d = v[u] - mu; q += d * d; }
#pragma unroll
    for (int o = 16; o; o >>= 1) q += __shfl_xor_sync(0xffffffffu, q, o);
    if (lane == 0) ws2[wid] = q;
    __syncthreads();
    float qs = 0.f;
#pragma unroll
    for (int w = 0; w < 8; w++) qs += ws2[w];
    const float r = rsqrtf(qs * (1.f / 1024.f) + 1e-5f);

#pragma unroll
    for (int u = 0; u < 4; u++) {
        const float val = (v[u] - mu) * r * g[tid + u * 256];
        const size_t o = (size_t)row * DMODEL + tid + u * 256;
        if (HL) {
            __half hv = __float2half_rn(val);
            yh[o] = *(uint16_t*)&hv;
        } else {
            y[o] = val;
        }
    }
}

// ---------------- fused one-shot converter ----------------
__device__ __forceinline__ uint2 h4pack(float4 v) {
    __half2 a = __floats2half2_rn(v.x, v.y);
    __half2 b = __floats2half2_rn(v.z, v.w);
    uint2 u; u.x = *(uint32_t*)&a; u.y = *(uint32_t*)&b;
    return u;
}

__global__ void __launch_bounds__(256) convert_all(
    const float4* __restrict__ x_in, float4* __restrict__ gx,
    uint2* __restrict__ xh,
    const float4* __restrict__ qw,  uint2* __restrict__ qo,
    const float4* __restrict__ aow, uint2* __restrict__ aoo,
    const float4* __restrict__ miw, uint2* __restrict__ mio,
    const float4* __restrict__ mow, uint2* __restrict__ moo,
    const float4* __restrict__ skw, uint2* __restrict__ sko)
{
    const int stride = gridDim.x * blockDim.x;
    const int g0 = blockIdx.x * blockDim.x + threadIdx.x;

    for (int i = g0; i < TOK * DMODEL / 4; i += stride) {
        float4 v = x_in[i];
        gx[i] = v;
        xh[i] = h4pack(v);
    }
    for (int i = g0; i < NL * DQKV * DMODEL / 4; i += stride) qo[i]  = h4pack(qw[i]);
    for (int i = g0; i < NL * DMODEL * DMODEL / 4; i += stride) aoo[i] = h4pack(aow[i]);
    for (int i = g0; i < NL * DFF * DMODEL / 4; i += stride) mio[i] = h4pack(miw[i]);
    for (int i = g0; i < NL * DMODEL * DFF / 4; i += stride) moo[i] = h4pack(mow[i]);
    for (int i = g0; i < 4 * DMODEL * 2 * DMODEL / 4; i += stride) {
        float4 v = skw[i];
        if (((i * 4) & 2047) >= 1024) {
            v.x *= 0.70710678118654752440f; v.y *= 0.70710678118654752440f;
            v.z *= 0.70710678118654752440f; v.w *= 0.70710678118654752440f;
        }
        sko[i] = h4pack(v);
    }
}

// ---------------- host orchestration ----------------
extern "C" void kernel_launch(void* const* d_in, const int* in_sizes, int n_in,
                              void* d_out, int out_size)
{
    (void)in_sizes; (void)n_in; (void)out_size;
    const float* x_in       = (const float*)d_in[0];
    const float* attn_w     = (const float*)d_in[1];
    const float* attn_out_w = (const float*)d_in[2];
    const float* mlp_ln_g   = (const float*)d_in[3];
    const float* mlp_in_w   = (const float*)d_in[4];
    const float* mlp_in_b   = (const float*)d_in[5];
    const float* mlp_out_w  = (const float*)d_in[6];
    const float* mlp_out_b  = (const float*)d_in[7];
    const float* skip_w     = (const float*)d_in[8];
    const float* skip_b     = (const float*)d_in[9];
    const float* out_ln_g   = (const float*)d_in[10];

    float* gx;
    cudaGetSymbolAddress((void**)&gx, g_x);

    __half *xA, *xB, *v2, *v3, *v4, *at, *ln, *ff, *qkvh, *qkvl;
    cudaGetSymbolAddress((void**)&xA, a_xA);
    cudaGetSymbolAddress((void**)&xB, a_xB);
    cudaGetSymbolAddress((void**)&v2, s_v2);
    cudaGetSymbolAddress((void**)&v3, s_v3);
    cudaGetSymbolAddress((void**)&v4, s_v4);
    cudaGetSymbolAddress((void**)&at, a_at);
    cudaGetSymbolAddress((void**)&ln, a_ln);
    cudaGetSymbolAddress((void**)&ff, a_ff);
    cudaGetSymbolAddress((void**)&qkvh, a_qkv_h);
    cudaGetSymbolAddress((void**)&qkvl, a_qkv_l);

    __half *wq, *wao, *wmi, *wmo, *wsk;
    cudaGetSymbolAddress((void**)&wq,  w_qkv);
    cudaGetSymbolAddress((void**)&wao, w_ao);
    cudaGetSymbolAddress((void**)&wmi, w_mi);
    cudaGetSymbolAddress((void**)&wmo, w_mo);
    cudaGetSymbolAddress((void**)&wsk, w_sk);

    cudaFuncSetAttribute((const void*)gemm_f16<256, false, 2, 2>, cudaFuncAttributeMaxDynamicSharedMemorySize, GSMEM_FM2);
    cudaFuncSetAttribute((const void*)gemm_f16<28,  false, 1, 3>, cudaFuncAttributeMaxDynamicSharedMemorySize, GSMEM_FM1);
    cudaFuncSetAttribute((const void*)gemm_f16<11,  false, 4, 2>, cudaFuncAttributeMaxDynamicSharedMemorySize, GSMEM_FM4);
    cudaFuncSetAttribute((const void*)gemm_f16<29,  false, 1, 3>, cudaFuncAttributeMaxDynamicSharedMemorySize, GSMEM_FM1);
    cudaFuncSetAttribute((const void*)gemm_f16<157, false, 1, 3>, cudaFuncAttributeMaxDynamicSharedMemorySize, GSMEM_FM1);
    cudaFuncSetAttribute((const void*)gemm_f16<25,  true,  1, 3>, cudaFuncAttributeMaxDynamicSharedMemorySize, GSMEM_FM1);
    cudaFuncSetAttribute(attn_hmma, cudaFuncAttributeMaxDynamicSharedMemorySize, ATTN_SMEM);

    convert_all<<<1184, 256>>>(
        (const float4*)x_in, (float4*)gx, (uint2*)xA,
        (const float4*)attn_w,     (uint2*)wq,
        (const float4*)attn_out_w, (uint2*)wao,
        (const float4*)mlp_in_w,   (uint2*)wmi,
        (const float4*)mlp_out_w,  (uint2*)wmo,
        (const float4*)skip_w,     (uint2*)wsk);

    __half* cur = xA;
    __half* alt = xB;

    for (int i = 0; i < NL; i++) {
        if (i >= 5) {
            __half* sv = (i == 5) ? v4 : (i == 6) ? v3 : v2;
            const int j = i - 4;
            gemm_f16<25, true, 1, 3><<<dim3(DMODEL / 128, TOK / 32), 256, GSMEM_FM1>>>(
                cur, sv,
                wsk + (size_t)j * DMODEL * 2 * DMODEL,
                skip_b + (size_t)j * DMODEL, nullptr,
                gx, (uint16_t*)alt, nullptr, nullptr, nullptr,
                DMODEL, 2 * DMODEL, 0);
            __half* t = cur; cur = alt; alt = t;
        }
        // QKV -> fp16 hi/lo (lo only for Q,K columns < 2048)
        gemm_f16<256, false, 2, 2><<<dim3(DQKV / 128, TOK / 64), 256, GSMEM_FM2>>>(
            cur, nullptr,
            wq + (size_t)i * DQKV * DMODEL,
            nullptr, nullptr, nullptr, nullptr,
            (uint16_t*)qkvh, (uint16_t*)qkvl, nullptr, DQKV, DMODEL, 2048);
        // attention (fp16: QK 3-term, PV 2-term) -> fp16
        attn_hmma<<<dim3(16, 16, 2), 128, ATTN_SMEM>>>(qkvh, qkvl, (uint16_t*)at);
        // attn out proj + residual -> x (fp32 + fp16)
        gemm_f16<28, false, 1, 3><<<dim3(DMODEL / 128, TOK / 32), 256, GSMEM_FM1>>>(
            at, nullptr,
            wao + (size_t)i * DMODEL * DMODEL,
            nullptr, gx, gx, (uint16_t*)cur, nullptr, nullptr, nullptr,
            DMODEL, DMODEL, 0);
        // MLP LN -> fp16
        ln_kernel2<true><<<TOK, 256>>>(gx, mlp_ln_g + (size_t)i * DMODEL,
                                       nullptr, (uint16_t*)ln);
        // MLP in + bias + gelu -> fp16
        gemm_f16<11, false, 4, 2><<<dim3(DFF / 128, TOK / 128), 256, GSMEM_FM4>>>(
            ln, nullptr,
            wmi + (size_t)i * DFF * DMODEL,
            mlp_in_b + (size_t)i * DFF, nullptr, nullptr,
            (uint16_t*)ff, nullptr, nullptr, nullptr, DFF, DMODEL, 0);
        // MLP out + bias + residual -> x (fp32 + fp16; layers 2/3/4 also save skip)
        if (i == 2 || i == 3 || i == 4) {
            __half* sv = (i == 2) ? v2 : (i == 3) ? v3 : v4;
            gemm_f16<157, false, 1, 3><<<dim3(DMODEL / 128, TOK / 32), 256, GSMEM_FM1>>>(
                ff, nullptr,
                wmo + (size_t)i * DMODEL * DFF,
                mlp_out_b + (size_t)i * DMODEL, gx, gx,
                (uint16_t*)cur, nullptr, nullptr, (uint16_t*)sv,
                DMODEL, DFF, 0);
        } else {
            gemm_f16<29, false, 1, 3><<<dim3(DMODEL / 128, TOK / 32), 256, GSMEM_FM1>>>(
                ff, nullptr,
                wmo + (size_t)i * DMODEL * DFF,
                mlp_out_b + (size_t)i * DMODEL, gx, gx,
                (uint16_t*)cur, nullptr, nullptr, nullptr, DMODEL, DFF, 0);
        }
    }

    ln_kernel2<false><<<TOK, 256>>>(gx, out_ln_g, (float*)d_out, nullptr);
}

// round 15
// speedup vs baseline: 1.1363x; 1.1363x over previous
#include <cuda_runtime.h>
#include <cuda_bf16.h>
#include <cuda_fp16.h>
#include <math.h>
#include <stdint.h>

// ---------------- problem constants ----------------
#define TOK    2048
#define DMODEL 1024
#define DQKV   3072
#define DFF    4096
#define NL     8

// ---------------- scratch (device globals, no allocs) ----------------
__device__ float g_x[TOK * DMODEL];
__device__ float g_part[2 * TOK * DMODEL];   // split-K partials

__device__ __half a_xA[TOK * DMODEL];
__device__ __half a_xB[TOK * DMODEL];
__device__ __half s_v2[TOK * DMODEL];
__device__ __half s_v3[TOK * DMODEL];
__device__ __half s_v4[TOK * DMODEL];
__device__ __half a_qkv_h[TOK * DQKV];
__device__ __half a_qkv_l[TOK * DQKV];
__device__ __half a_at[TOK * DMODEL];
__device__ __half a_ln[TOK * DMODEL];
__device__ __half a_ff[TOK * DFF];
__device__ __half w_qkv[NL * DQKV * DMODEL];
__device__ __half w_ao [NL * DMODEL * DMODEL];
__device__ __half w_mi [NL * DFF * DMODEL];
__device__ __half w_mo [NL * DMODEL * DFF];
__device__ __half w_sk [4 * DMODEL * 2 * DMODEL];  // cols >=1024 pre-scaled by 2^-0.5

// ---------------- helpers ----------------
__device__ __forceinline__ uint32_t smem_u32(const void* p) {
    uint32_t a;
    asm("{ .reg .u64 t; cvta.to.shared.u64 t, %1; cvt.u32.u64 %0, t; }"
        : "=r"(a) : "l"(p));
    return a;
}

__device__ __forceinline__ void cp16(uint32_t dst, const void* src) {
    asm volatile("cp.async.cg.shared.global [%0], [%1], 16;" :: "r"(dst), "l"(src));
}

__device__ __forceinline__ void ldm_x4(uint32_t addr, uint32_t& r0, uint32_t& r1,
                                       uint32_t& r2, uint32_t& r3) {
    asm volatile("ldmatrix.sync.aligned.m8n8.x4.shared.b16 {%0,%1,%2,%3}, [%4];"
                 : "=r"(r0), "=r"(r1), "=r"(r2), "=r"(r3) : "r"(addr));
}

__device__ __forceinline__ void ldm_x4t(uint32_t addr, uint32_t& r0, uint32_t& r1,
                                        uint32_t& r2, uint32_t& r3) {
    asm volatile("ldmatrix.sync.aligned.m8n8.x4.trans.shared.b16 {%0,%1,%2,%3}, [%4];"
                 : "=r"(r0), "=r"(r1), "=r"(r2), "=r"(r3) : "r"(addr));
}

__device__ __forceinline__ void mma_fp(float* c, const uint32_t* a,
                                       uint32_t b0, uint32_t b1) {
    asm volatile(
        "mma.sync.aligned.m16n8k16.row.col.f32.f16.f16.f32 "
        "{%0,%1,%2,%3}, {%4,%5,%6,%7}, {%8,%9}, {%0,%1,%2,%3};"
        : "+f"(c[0]), "+f"(c[1]), "+f"(c[2]), "+f"(c[3])
        : "r"(a[0]), "r"(a[1]), "r"(a[2]), "r"(a[3]), "r"(b0), "r"(b1));
}

__device__ __forceinline__ void split_h(float v, uint16_t& h, uint16_t& l) {
    __half hb = __float2half_rn(v);
    __half lb = __float2half_rn(v - __half2float(hb));
    h = *(uint16_t*)&hb;
    l = *(uint16_t*)&lb;
}

// ---------------- single-fp16 HMMA GEMM (R13 config + optional split-K) -----
// C = act(A * W^T + bias)(+res); A, W single fp16. lda = row stride of A and W.
// SPLITK: blockIdx.z selects K-half; C written at z*TOK*N offset; no bias/act.
// FLAGS: 1=bias, 2=gelu, 4=residual(fp32), 8=write fp16, 16=write fp32,
//        128=also write fp16 to Cb2, 256=write fp16 hi/lo (lo only c0<lo_limit)
#define GBK   32
#define GROWB 80
#define GNST  4

template<int FLAGS, bool SPLITA, int FM, int MINB, bool SPLITK>
__global__ void __launch_bounds__(256, MINB) gemm_f16(
    const __half* __restrict__ Ah, const __half* __restrict__ A2h,
    const __half* __restrict__ W,
    const float* __restrict__ bias, const float* __restrict__ res,
    float* __restrict__ C, uint16_t* __restrict__ Cb,
    uint16_t* __restrict__ Cph, uint16_t* __restrict__ Cpl,
    uint16_t* __restrict__ Cb2, int N, int K, int lo_limit, int lda)
{
    constexpr int BM     = FM * 32;
    constexpr int ATILEB = BM * GROWB;
    constexpr int WTILEB = 128 * GROWB;
    constexpr int STRIDE = ATILEB + WTILEB;

    extern __shared__ char smem[];
    const uint32_t sb = smem_u32(smem);
    const int tid  = threadIdx.x;
    const int wid  = tid >> 5;
    const int lane = tid & 31;
    const int wm   = wid >> 2;
    const int wn   = wid & 3;
    const int bm   = blockIdx.y * BM;
    const int bn   = blockIdx.x * 128;
    const size_t kbase = SPLITK ? (size_t)blockIdx.z * K : 0;

    const int a_r = (FM == 4) ? (tid >> 1) : (tid >> 2);
    const int a_c = (FM == 4) ? ((tid & 1) * 16) : ((tid & 3) * 8);
    const uint32_t sA = (uint32_t)a_r * GROWB + a_c * 2;
    const size_t a_goffK = (size_t)(bm + a_r) * lda + a_c;
    const size_t a_goff1 = (size_t)(bm + a_r) * 1024 + a_c;
    const int w_r = tid >> 1;
    const int w_c = (tid & 1) * 16;
    const uint32_t sW = (uint32_t)(ATILEB) + (uint32_t)w_r * GROWB + w_c * 2;
    const size_t w_goff = (size_t)(bn + w_r) * lda + w_c;

    auto load_stage = [&](int s) {
        const uint32_t base = sb + (uint32_t)(s & (GNST - 1)) * STRIDE;
        const size_t ko = (size_t)s * GBK + kbase;
        const __half* pa;
        if (SPLITA) {
            pa = (ko >= 1024) ? (A2h + a_goff1 + (ko - 1024)) : (Ah + a_goff1 + ko);
        } else {
            pa = Ah + a_goffK + ko;
        }
        if (FM == 4) {
            cp16(base + sA,      pa);
            cp16(base + sA + 16, pa + 8);
        } else {
            cp16(base + sA, pa);
        }
        const __half* pw = W + w_goff + ko;
        cp16(base + sW,      pw);
        cp16(base + sW + 16, pw + 8);
        asm volatile("cp.async.commit_group;");
    };

    const int S = K / GBK;
    for (int s = 0; s < GNST - 1; s++) load_stage(s);

    float acc[FM][4][4];
#pragma unroll
    for (int i = 0; i < FM; i++)
#pragma unroll
        for (int j = 0; j < 4; j++)
#pragma unroll
            for (int k = 0; k < 4; k++) acc[i][j][k] = 0.f;

    const uint32_t aoff = (uint32_t)(wm * (FM * 16) + (lane & 15)) * GROWB
                        + (lane >> 4) * 16;
    const uint32_t boff = (uint32_t)(wn * 32 + (lane & 7) + ((lane >> 4) & 1) * 8) * GROWB
                        + ((lane >> 3) & 1) * 16 + ATILEB;

    for (int s = 0; s < S; s++) {
        asm volatile("cp.async.wait_group %0;" :: "n"(GNST - 2) : "memory");
        __syncthreads();

        const int pf = s + GNST - 1;
        if (pf < S) load_stage(pf);
        else        asm volatile("cp.async.commit_group;");

        const uint32_t base = sb + (uint32_t)(s & (GNST - 1)) * STRIDE;
        if (FM == 2) {
            uint32_t ah[2][2][4], bb[2][2][4];
#pragma unroll
            for (int k16 = 0; k16 < 2; k16++) {
#pragma unroll
                for (int fm = 0; fm < 2; fm++) {
                    const uint32_t ao = base + aoff + fm * 16 * GROWB + k16 * 32;
                    ldm_x4(ao, ah[k16][fm][0], ah[k16][fm][1],
                               ah[k16][fm][2], ah[k16][fm][3]);
                }
#pragma unroll
                for (int fnp = 0; fnp < 2; fnp++) {
                    const uint32_t bo = base + boff + fnp * 16 * GROWB + k16 * 32;
                    ldm_x4(bo, bb[k16][fnp][0], bb[k16][fnp][1],
                               bb[k16][fnp][2], bb[k16][fnp][3]);
                }
            }
#pragma unroll
            for (int k16 = 0; k16 < 2; k16++)
#pragma unroll
                for (int fm = 0; fm < 2; fm++)
#pragma unroll
                    for (int fnp = 0; fnp < 2; fnp++) {
                        mma_fp(acc[fm][fnp * 2 + 0], ah[k16][fm],
                               bb[k16][fnp][0], bb[k16][fnp][1]);
                        mma_fp(acc[fm][fnp * 2 + 1], ah[k16][fm],
                               bb[k16][fnp][2], bb[k16][fnp][3]);
                    }
        } else {
#pragma unroll
            for (int k16 = 0; k16 < 2; k16++) {
                uint32_t ah[FM][4], bb[2][4];
#pragma unroll
                for (int fm = 0; fm < FM; fm++) {
                    const uint32_t ao = base + aoff + fm * 16 * GROWB + k16 * 32;
                    ldm_x4(ao, ah[fm][0], ah[fm][1], ah[fm][2], ah[fm][3]);
                }
#pragma unroll
                for (int fnp = 0; fnp < 2; fnp++) {
                    const uint32_t bo = base + boff + fnp * 16 * GROWB + k16 * 32;
                    ldm_x4(bo, bb[fnp][0], bb[fnp][1], bb[fnp][2], bb[fnp][3]);
                }
#pragma unroll
                for (int fm = 0; fm < FM; fm++) {
#pragma unroll
                    for (int fnp = 0; fnp < 2; fnp++) {
                        mma_fp(acc[fm][fnp * 2 + 0], ah[fm], bb[fnp][0], bb[fnp][1]);
                        mma_fp(acc[fm][fnp * 2 + 1], ah[fm], bb[fnp][2], bb[fnp][3]);
                    }
                }
            }
        }
    }

    // ---- epilogue ----
    float* Cw = C + (SPLITK ? (size_t)blockIdx.z * TOK * N : 0);
#pragma unroll
    for (int fm = 0; fm < FM; fm++) {
#pragma unroll
        for (int fn = 0; fn < 4; fn++) {
            const int r0 = bm + wm * (FM * 16) + fm * 16 + (lane >> 2);
            const int c0 = bn + wn * 32 + fn * 8 + (lane & 3) * 2;
            float v[4] = { acc[fm][fn][0], acc[fm][fn][1],
                           acc[fm][fn][2], acc[fm][fn][3] };
            if (FLAGS & 1) {
                const float b0 = __ldg(bias + c0), b1 = __ldg(bias + c0 + 1);
                v[0] += b0; v[1] += b1; v[2] += b0; v[3] += b1;
            }
            if (FLAGS & 2) {
#pragma unroll
                for (int u = 0; u < 4; u++)
                    v[u] = 0.5f * v[u] * (1.f + erff(v[u] * 0.7071067811865476f));
            }
            if (FLAGS & 4) {
                const float2 ra = *(const float2*)(res + (size_t)r0 * N + c0);
                const float2 rb = *(const float2*)(res + (size_t)(r0 + 8) * N + c0);
                v[0] += ra.x; v[1] += ra.y; v[2] += rb.x; v[3] += rb.y;
            }
            if (FLAGS & 16) {
                float2 oa; oa.x = v[0]; oa.y = v[1];
                float2 ob; ob.x = v[2]; ob.y = v[3];
                *(float2*)(Cw + (size_t)r0 * N + c0) = oa;
                *(float2*)(Cw + (size_t)(r0 + 8) * N + c0) = ob;
            }
            if (FLAGS & 8) {
#pragma unroll
                for (int hf = 0; hf < 2; hf++) {
                    const int rr = r0 + hf * 8;
                    __half2 p = __floats2half2_rn(v[hf * 2 + 0], v[hf * 2 + 1]);
                    *(uint32_t*)(Cb + (size_t)rr * N + c0) = *(uint32_t*)&p;
                    if (FLAGS & 128)
                        *(uint32_t*)(Cb2 + (size_t)rr * N + c0) = *(uint32_t*)&p;
                }
            }
            if (FLAGS & 256) {
                uint16_t h0, l0, h1, l1;
                const bool store_lo = c0 < lo_limit;
#pragma unroll
                for (int hf = 0; hf < 2; hf++) {
                    const int rr = r0 + hf * 8;
                    split_h(v[hf * 2 + 0], h0, l0);
                    split_h(v[hf * 2 + 1], h1, l1);
                    *(uint32_t*)(Cph + (size_t)rr * N + c0) = (uint32_t)h0 | ((uint32_t)h1 << 16);
                    if (store_lo)
                        *(uint32_t*)(Cpl + (size_t)rr * N + c0) = (uint32_t)l0 | ((uint32_t)l1 << 16);
                }
            }
        }
    }
}

// GEMM smem sizes (NST=4)
#define GSMEM_FM4 ((128 * GROWB + 128 * GROWB) * GNST)   // 81920
#define GSMEM_FM2 ((64 * GROWB + 128 * GROWB) * GNST)    // 61440

// ---------------- split-K reduce: gx += p0+p1+bias; cur=fp16(gx); opt sv ----
__global__ void __launch_bounds__(256) splitk_reduce(
    const float4* __restrict__ part, const float4* __restrict__ bias,
    float4* __restrict__ gx, uint2* __restrict__ cur, uint2* __restrict__ sv)
{
    const int i = blockIdx.x * blockDim.x + threadIdx.x;   // over TOK*DMODEL/4
    const float4 p0 = part[i];
    const float4 p1 = part[i + TOK * DMODEL / 4];
    const float4 b  = bias[i & (DMODEL / 4 - 1)];
    float4 x = gx[i];
    x.x += p0.x + p1.x + b.x;
    x.y += p0.y + p1.y + b.y;
    x.z += p0.z + p1.z + b.z;
    x.w += p0.w + p1.w + b.w;
    gx[i] = x;
    __half2 a = __floats2half2_rn(x.x, x.y);
    __half2 c = __floats2half2_rn(x.z, x.w);
    uint2 u; u.x = *(uint32_t*)&a; u.y = *(uint32_t*)&c;
    cur[i] = u;
    if (sv) sv[i] = u;
}

// ---------------- fp16 flash attention (QK 3-term, PV 2-term) ---------------
#define ASTR 144
#define ATB  (64 * ASTR)
#define ATTN_SMEM (8 * ATB)

__global__ void __launch_bounds__(128) attn_hmma(
    const __half* __restrict__ qh, const __half* __restrict__ ql,
    uint16_t* __restrict__ out)
{
    extern __shared__ char smc[];
    const uint32_t sb = smem_u32(smc);
    const int b = blockIdx.z, h = blockIdx.y, q0 = blockIdx.x * 64;
    const int tid = threadIdx.x, wid = tid >> 5, lane = tid & 31;
    const float slope = -exp2f(-0.5f * (float)(h + 1));
    const size_t base = (size_t)b * 1024 * DQKV + (size_t)h * 64;

    {
        const int which = tid >> 6, r = tid & 63;
        const __half* src = (which ? ql : qh) + base + (size_t)(q0 + r) * DQKV;
        const uint32_t dst = sb + which * ATB + r * ASTR;
#pragma unroll
        for (int c = 0; c < 8; c++) cp16(dst + c * 16, src + c * 8);
        asm volatile("cp.async.commit_group;");
    }

    auto load_kv = [&](int t) {
        const uint32_t bufb = sb + 2 * ATB + (t & 1) * (3 * ATB);
        if (wid < 2) {
            const __half* sp = (wid ? ql : qh) + base + 1024;
#pragma unroll
            for (int rr = 0; rr < 2; rr++) {
                const int r = lane + rr * 32;
                const __half* src = sp + (size_t)(t * 64 + r) * DQKV;
                const uint32_t dst = bufb + wid * ATB + r * ASTR;
#pragma unroll
                for (int c = 0; c < 8; c++) cp16(dst + c * 16, src + c * 8);
            }
        } else {
            const int r = (wid - 2) * 32 + lane;
            const __half* src = qh + base + 2048 + (size_t)(t * 64 + r) * DQKV;
            const uint32_t dst = bufb + 2 * ATB + r * ASTR;
#pragma unroll
            for (int c = 0; c < 8; c++) cp16(dst + c * 16, src + c * 8);
        }
        asm volatile("cp.async.commit_group;");
    };

    load_kv(0);
    asm volatile("cp.async.wait_group 0;" ::: "memory");
    __syncthreads();

    uint32_t qfh[4][4], qfl[4][4];
    {
        const uint32_t ao = sb + (uint32_t)(wid * 16 + (lane & 15)) * ASTR + (lane >> 4) * 16;
#pragma unroll
        for (int kk = 0; kk < 4; kk++) {
            ldm_x4(ao + kk * 32,       qfh[kk][0], qfh[kk][1], qfh[kk][2], qfh[kk][3]);
            ldm_x4(ao + ATB + kk * 32, qfl[kk][0], qfl[kk][1], qfl[kk][2], qfl[kk][3]);
        }
        const __half2 sc = __floats2half2_rn(0.125f, 0.125f);
#pragma unroll
        for (int kk = 0; kk < 4; kk++)
#pragma unroll
            for (int u = 0; u < 4; u++) {
                __half2 vh = *(__half2*)&qfh[kk][u];
                __half2 vl = *(__half2*)&qfl[kk][u];
                vh = __hmul2(vh, sc); vl = __hmul2(vl, sc);
                qfh[kk][u] = *(uint32_t*)&vh; qfl[kk][u] = *(uint32_t*)&vl;
            }
    }

    const int rA = q0 + wid * 16 + (lane >> 2);
    const int rB = rA + 8;
    const bool okA = rA < 1023, okB = rB < 1023;

    float m0 = -1e30f, m1 = -1e30f, l0s = 0.f, l1s = 0.f;
    float oacc[8][4];
#pragma unroll
    for (int j = 0; j < 8; j++)
#pragma unroll
        for (int u = 0; u < 4; u++) oacc[j][u] = 0.f;

    for (int t = 0; t < 16; t++) {
        if (t > 0) {
            asm volatile("cp.async.wait_group 0;" ::: "memory");
            __syncthreads();
        }
        if (t < 15) load_kv(t + 1);

        const uint32_t kb = sb + 2 * ATB + (t & 1) * (3 * ATB);
        const uint32_t vb = kb + 2 * ATB;

        float s[8][4];
#pragma unroll
        for (int j = 0; j < 8; j++)
#pragma unroll
            for (int u = 0; u < 4; u++) s[j][u] = 0.f;

        const uint32_t bbase = kb + (uint32_t)((lane & 7) + ((lane >> 4) & 1) * 8) * ASTR
                             + ((lane >> 3) & 1) * 16;
#pragma unroll
        for (int kk = 0; kk < 4; kk++) {
#pragma unroll
            for (int nb = 0; nb < 4; nb++) {
                uint32_t b0, b1, b2, b3, c0, c1, c2, c3;
                const uint32_t ad = bbase + nb * 16 * ASTR + kk * 32;
                ldm_x4(ad,       b0, b1, b2, b3);
                ldm_x4(ad + ATB, c0, c1, c2, c3);
                mma_fp(s[nb*2],   qfh[kk], b0, b1);
                mma_fp(s[nb*2],   qfl[kk], b0, b1);
                mma_fp(s[nb*2],   qfh[kk], c0, c1);
                mma_fp(s[nb*2+1], qfh[kk], b2, b3);
                mma_fp(s[nb*2+1], qfl[kk], b2, b3);
                mma_fp(s[nb*2+1], qfh[kk], c2, c3);
            }
        }

        float tmax0 = -1e30f, tmax1 = -1e30f;
#pragma unroll
        for (int j = 0; j < 8; j++) {
            const int kj = t * 64 + j * 8 + (lane & 3) * 2;
            const bool k0ok = kj < 1023, k1ok = kj + 1 < 1023;
            s[j][0] += (okA && k0ok) ? slope * fabsf((float)(rA - kj))     : 0.f;
            s[j][1] += (okA && k1ok) ? slope * fabsf((float)(rA - kj - 1)) : 0.f;
            s[j][2] += (okB && k0ok) ? slope * fabsf((float)(rB - kj))     : 0.f;
            s[j][3] += (okB && k1ok) ? slope * fabsf((float)(rB - kj - 1)) : 0.f;
            tmax0 = fmaxf(tmax0, fmaxf(s[j][0], s[j][1]));
            tmax1 = fmaxf(tmax1, fmaxf(s[j][2], s[j][3]));
        }
        tmax0 = fmaxf(tmax0, __shfl_xor_sync(0xffffffffu, tmax0, 1));
        tmax0 = fmaxf(tmax0, __shfl_xor_sync(0xffffffffu, tmax0, 2));
        tmax1 = fmaxf(tmax1, __shfl_xor_sync(0xffffffffu, tmax1, 1));
        tmax1 = fmaxf(tmax1, __shfl_xor_sync(0xffffffffu, tmax1, 2));

        const float mn0 = fmaxf(m0, tmax0), mn1 = fmaxf(m1, tmax1);
        const float al0 = __expf(m0 - mn0), al1 = __expf(m1 - mn1);
        m0 = mn0; m1 = mn1;

        float rs0 = 0.f, rs1 = 0.f;
#pragma unroll
        for (int j = 0; j < 8; j++) {
            s[j][0] = __expf(s[j][0] - mn0); rs0 += s[j][0];
            s[j][1] = __expf(s[j][1] - mn0); rs0 += s[j][1];
            s[j][2] = __expf(s[j][2] - mn1); rs1 += s[j][2];
            s[j][3] = __expf(s[j][3] - mn1); rs1 += s[j][3];
        }
        rs0 += __shfl_xor_sync(0xffffffffu, rs0, 1);
        rs0 += __shfl_xor_sync(0xffffffffu, rs0, 2);
        rs1 += __shfl_xor_sync(0xffffffffu, rs1, 1);
        rs1 += __shfl_xor_sync(0xffffffffu, rs1, 2);
        l0s = l0s * al0 + rs0;
        l1s = l1s * al1 + rs1;
#pragma unroll
        for (int j = 0; j < 8; j++) {
            oacc[j][0] *= al0; oacc[j][1] *= al0;
            oacc[j][2] *= al1; oacc[j][3] *= al1;
        }

        uint32_t pfh[4][4], pfl[4][4];
#pragma unroll
        for (int kk = 0; kk < 4; kk++) {
#pragma unroll
            for (int half = 0; half < 2; half++) {
                const int j = 2 * kk + half;
                uint16_t h0, l0, h1, l1, h2, l2, h3, l3;
                split_h(s[j][0], h0, l0); split_h(s[j][1], h1, l1);
                split_h(s[j][2], h2, l2); split_h(s[j][3], h3, l3);
                pfh[kk][half*2+0] = (uint32_t)h0 | ((uint32_t)h1 << 16);
                pfh[kk][half*2+1] = (uint32_t)h2 | ((uint32_t)h3 << 16);
                pfl[kk][half*2+0] = (uint32_t)l0 | ((uint32_t)l1 << 16);
                pfl[kk][half*2+1] = (uint32_t)l2 | ((uint32_t)l3 << 16);
            }
        }

        const uint32_t vbase = vb + (uint32_t)(((lane >> 3) & 1) * 8 + (lane & 7)) * ASTR
                             + (lane >> 4) * 16;
#pragma unroll
        for (int kk = 0; kk < 4; kk++) {
#pragma unroll
            for (int nb = 0; nb < 4; nb++) {
                uint32_t v0, v1, v2, v3;
                const uint32_t ad = vbase + kk * 16 * ASTR + nb * 32;
                ldm_x4t(ad, v0, v1, v2, v3);
                mma_fp(oacc[nb*2],   pfh[kk], v0, v1);
                mma_fp(oacc[nb*2],   pfl[kk], v0, v1);
                mma_fp(oacc[nb*2+1], pfh[kk], v2, v3);
                mma_fp(oacc[nb*2+1], pfl[kk], v2, v3);
            }
        }
    }

    const float inv0 = 1.f / l0s, inv1 = 1.f / l1s;
#pragma unroll
    for (int j = 0; j < 8; j++) {
        const int d0 = j * 8 + (lane & 3) * 2;
        size_t o = ((size_t)b * 1024 + rA) * DMODEL + h * 64 + d0;
        __half2 pa = __floats2half2_rn(oacc[j][0] * inv0, oacc[j][1] * inv0);
        *(uint32_t*)(out + o) = *(uint32_t*)&pa;
        o += (size_t)8 * DMODEL;
        __half2 pb = __floats2half2_rn(oacc[j][2] * inv1, oacc[j][3] * inv1);
        *(uint32_t*)(out + o) = *(uint32_t*)&pb;
    }
}

// ---------------- LayerNorm (warp-shuffle reduction) ----------------
template<bool HL>
__global__ void __launch_bounds__(256) ln_kernel2(
    const float* __restrict__ x, const float* __restrict__ g,
    float* __restrict__ y, uint16_t* __restrict__ yh)
{
    __shared__ float ws1[8], ws2[8];
    const int row = blockIdx.x;
    const int tid = threadIdx.x;
    const int wid = tid >> 5, lane = tid & 31;
    const float* xr = x + (size_t)row * DMODEL;

    float v[4];
    float s = 0.f;
#pragma unroll
    for (int u = 0; u < 4; u++) { v[u] = xr[tid + u * 256]; s += v[u]; }
#pragma unroll
    for (int o = 16; o; o >>= 1) s += __shfl_xor_sync(0xffffffffu, s, o);
    if (lane == 0) ws1[wid] = s;
    __syncthreads();
    float sum = 0.f;
#pragma unroll
    for (int w = 0; w < 8; w++) sum += ws1[w];
    const float mu = sum * (1.f / 1024.f);

    float q = 0.f;
#pragma unroll
    for (int u = 0; u < 4; u++) { const float d = v[u] - mu; q += d * d; }
#pragma unroll
    for (int o = 16; o; o >>= 1) q += __shfl_xor_sync(0xffffffffu, q, o);
    if (lane == 0) ws2[wid] = q;
    __syncthreads();
    float qs = 0.f;
#pragma unroll
    for (int w = 0; w < 8; w++) qs += ws2[w];
    const float r = rsqrtf(qs * (1.f / 1024.f) + 1e-5f);

#pragma unroll
    for (int u = 0; u < 4; u++) {
        const float val = (v[u] - mu) * r * g[tid + u * 256];
        const size_t o = (size_t)row * DMODEL + tid + u * 256;
        if (HL) {
            __half hv = __float2half_rn(val);
            yh[o] = *(uint16_t*)&hv;
        } else {
            y[o] = val;
        }
    }
}

// ---------------- fused one-shot converter ----------------
__device__ __forceinline__ uint2 h4pack(float4 v) {
    __half2 a = __floats2half2_rn(v.x, v.y);
    __half2 b = __floats2half2_rn(v.z, v.w);
    uint2 u; u.x = *(uint32_t*)&a; u.y = *(uint32_t*)&b;
    return u;
}

__global__ void __launch_bounds__(256) convert_all(
    const float4* __restrict__ x_in, float4* __restrict__ gx,
    uint2* __restrict__ xh,
    const float4* __restrict__ qw,  uint2* __restrict__ qo,
    const float4* __restrict__ aow, uint2* __restrict__ aoo,
    const float4* __restrict__ miw, uint2* __restrict__ mio,
    const float4* __restrict__ mow, uint2* __restrict__ moo,
    const float4* __restrict__ skw, uint2* __restrict__ sko)
{
    const int stride = gridDim.x * blockDim.x;
    const int g0 = blockIdx.x * blockDim.x + threadIdx.x;

    for (int i = g0; i < TOK * DMODEL / 4; i += stride) {
        float4 v = x_in[i];
        gx[i] = v;
        xh[i] = h4pack(v);
    }
    for (int i = g0; i < NL * DQKV * DMODEL / 4; i += stride) qo[i]  = h4pack(qw[i]);
    for (int i = g0; i < NL * DMODEL * DMODEL / 4; i += stride) aoo[i] = h4pack(aow[i]);
    for (int i = g0; i < NL * DFF * DMODEL / 4; i += stride) mio[i] = h4pack(miw[i]);
    for (int i = g0; i < NL * DMODEL * DFF / 4; i += stride) moo[i] = h4pack(mow[i]);
    for (int i = g0; i < 4 * DMODEL * 2 * DMODEL / 4; i += stride) {
        float4 v = skw[i];
        if (((i * 4) & 2047) >= 1024) {
            v.x *= 0.70710678118654752440f; v.y *= 0.70710678118654752440f;
            v.z *= 0.70710678118654752440f; v.w *= 0.70710678118654752440f;
        }
        sko[i] = h4pack(v);
    }
}

// ---------------- host orchestration ----------------
extern "C" void kernel_launch(void* const* d_in, const int* in_sizes, int n_in,
                              void* d_out, int out_size)
{
    (void)in_sizes; (void)n_in; (void)out_size;
    const float* x_in       = (const float*)d_in[0];
    const float* attn_w     = (const float*)d_in[1];
    const float* attn_out_w = (const float*)d_in[2];
    const float* mlp_ln_g   = (const float*)d_in[3];
    const float* mlp_in_w   = (const float*)d_in[4];
    const float* mlp_in_b   = (const float*)d_in[5];
    const float* mlp_out_w  = (const float*)d_in[6];
    const float* mlp_out_b  = (const float*)d_in[7];
    const float* skip_w     = (const float*)d_in[8];
    const float* skip_b     = (const float*)d_in[9];
    const float* out_ln_g   = (const float*)d_in[10];

    float *gx, *gpart;
    cudaGetSymbolAddress((void**)&gx,    g_x);
    cudaGetSymbolAddress((void**)&gpart, g_part);

    __half *xA, *xB, *v2, *v3, *v4, *at, *ln, *ff, *qkvh, *qkvl;
    cudaGetSymbolAddress((void**)&xA, a_xA);
    cudaGetSymbolAddress((void**)&xB, a_xB);
    cudaGetSymbolAddress((void**)&v2, s_v2);
    cudaGetSymbolAddress((void**)&v3, s_v3);
    cudaGetSymbolAddress((void**)&v4, s_v4);
    cudaGetSymbolAddress((void**)&at, a_at);
    cudaGetSymbolAddress((void**)&ln, a_ln);
    cudaGetSymbolAddress((void**)&ff, a_ff);
    cudaGetSymbolAddress((void**)&qkvh, a_qkv_h);
    cudaGetSymbolAddress((void**)&qkvl, a_qkv_l);

    __half *wq, *wao, *wmi, *wmo, *wsk;
    cudaGetSymbolAddress((void**)&wq,  w_qkv);
    cudaGetSymbolAddress((void**)&wao, w_ao);
    cudaGetSymbolAddress((void**)&wmi, w_mi);
    cudaGetSymbolAddress((void**)&wmo, w_mo);
    cudaGetSymbolAddress((void**)&wsk, w_sk);

    cudaFuncSetAttribute((const void*)gemm_f16<256, false, 2, 2, false>, cudaFuncAttributeMaxDynamicSharedMemorySize, GSMEM_FM2);
    cudaFuncSetAttribute((const void*)gemm_f16<28,  false, 2, 2, false>, cudaFuncAttributeMaxDynamicSharedMemorySize, GSMEM_FM2);
    cudaFuncSetAttribute((const void*)gemm_f16<11,  false, 4, 2, false>, cudaFuncAttributeMaxDynamicSharedMemorySize, GSMEM_FM4);
    cudaFuncSetAttribute((const void*)gemm_f16<16,  false, 2, 2, true>,  cudaFuncAttributeMaxDynamicSharedMemorySize, GSMEM_FM2);
    cudaFuncSetAttribute((const void*)gemm_f16<25,  true,  2, 2, false>, cudaFuncAttributeMaxDynamicSharedMemorySize, GSMEM_FM2);
    cudaFuncSetAttribute(attn_hmma, cudaFuncAttributeMaxDynamicSharedMemorySize, ATTN_SMEM);

    convert_all<<<1184, 256>>>(
        (const float4*)x_in, (float4*)gx, (uint2*)xA,
        (const float4*)attn_w,     (uint2*)wq,
        (const float4*)attn_out_w, (uint2*)wao,
        (const float4*)mlp_in_w,   (uint2*)wmi,
        (const float4*)mlp_out_w,  (uint2*)wmo,
        (const float4*)skip_w,     (uint2*)wsk);

    __half* cur = xA;
    __half* alt = xB;

    for (int i = 0; i < NL; i++) {
        if (i >= 5) {
            __half* sv = (i == 5) ? v4 : (i == 6) ? v3 : v2;
            const int j = i - 4;
            gemm_f16<25, true, 2, 2, false><<<dim3(DMODEL / 128, TOK / 64), 256, GSMEM_FM2>>>(
                cur, sv,
                wsk + (size_t)j * DMODEL * 2 * DMODEL,
                skip_b + (size_t)j * DMODEL, nullptr,
                gx, (uint16_t*)alt, nullptr, nullptr, nullptr,
                DMODEL, 2 * DMODEL, 0, 2 * DMODEL);
            __half* t = cur; cur = alt; alt = t;
        }
        // QKV -> fp16 hi/lo (lo only for Q,K columns < 2048)
        gemm_f16<256, false, 2, 2, false><<<dim3(DQKV / 128, TOK / 64), 256, GSMEM_FM2>>>(
            cur, nullptr,
            wq + (size_t)i * DQKV * DMODEL,
            nullptr, nullptr, nullptr, nullptr,
            (uint16_t*)qkvh, (uint16_t*)qkvl, nullptr, DQKV, DMODEL, 2048, DMODEL);
        // attention (fp16: QK 3-term, PV 2-term) -> fp16
        attn_hmma<<<dim3(16, 16, 2), 128, ATTN_SMEM>>>(qkvh, qkvl, (uint16_t*)at);
        // attn out proj + residual -> x (fp32 + fp16)
        gemm_f16<28, false, 2, 2, false><<<dim3(DMODEL / 128, TOK / 64), 256, GSMEM_FM2>>>(
            at, nullptr,
            wao + (size_t)i * DMODEL * DMODEL,
            nullptr, gx, gx, (uint16_t*)cur, nullptr, nullptr, nullptr,
            DMODEL, DMODEL, 0, DMODEL);
        // MLP LN -> fp16
        ln_kernel2<true><<<TOK, 256>>>(gx, mlp_ln_g + (size_t)i * DMODEL,
                                       nullptr, (uint16_t*)ln);
        // MLP in + bias + gelu -> fp16
        gemm_f16<11, false, 4, 2, false><<<dim3(DFF / 128, TOK / 128), 256, GSMEM_FM4>>>(
            ln, nullptr,
            wmi + (size_t)i * DFF * DMODEL,
            mlp_in_b + (size_t)i * DFF, nullptr, nullptr,
            (uint16_t*)ff, nullptr, nullptr, nullptr, DFF, DMODEL, 0, DMODEL);
        // MLP out: split-K x2 partials, then fused reduce (+bias+res+fp16+save)
        gemm_f16<16, false, 2, 2, true><<<dim3(DMODEL / 128, TOK / 64, 2), 256, GSMEM_FM2>>>(
            ff, nullptr,
            wmo + (size_t)i * DMODEL * DFF,
            nullptr, nullptr, gpart, nullptr, nullptr, nullptr, nullptr,
            DMODEL, DFF / 2, 0, DFF);
        {
            __half* sv = (i == 2) ? v2 : (i == 3) ? v3 : (i == 4) ? v4 : nullptr;
            splitk_reduce<<<TOK * DMODEL / 4 / 256, 256>>>(
                (const float4*)gpart,
                (const float4*)(mlp_out_b + (size_t)i * DMODEL),
                (float4*)gx, (uint2*)cur, (uint2*)sv);
        }
    }

    ln_kernel2<false><<<TOK, 256>>>(gx, out_ln_g, (float*)d_out, nullptr);
}

// round 16
// speedup vs baseline: 1.2138x; 1.0682x over previous
#include <cuda_runtime.h>
#include <cuda_bf16.h>
#include <cuda_fp16.h>
#include <math.h>
#include <stdint.h>

// ---------------- problem constants ----------------
#define TOK    2048
#define DMODEL 1024
#define DQKV   3072
#define DFF    4096
#define NL     8

// ---------------- scratch (device globals, no allocs) ----------------
__device__ float g_x[TOK * DMODEL];

__device__ __half a_xA[TOK * DMODEL];
__device__ __half a_xB[TOK * DMODEL];
__device__ __half s_v2[TOK * DMODEL];
__device__ __half s_v3[TOK * DMODEL];
__device__ __half s_v4[TOK * DMODEL];
__device__ __half a_qkv_h[TOK * DQKV];
__device__ __half a_qkv_l[TOK * DQKV];
__device__ __half a_at[TOK * DMODEL];
__device__ __half a_ln[TOK * DMODEL];
__device__ __half a_ff[TOK * DFF];
__device__ __half w_qkv[NL * DQKV * DMODEL];
__device__ __half w_ao [NL * DMODEL * DMODEL];
__device__ __half w_mi [NL * DFF * DMODEL];
__device__ __half w_mo [NL * DMODEL * DFF];
__device__ __half w_sk [4 * DMODEL * 2 * DMODEL];  // cols >=1024 pre-scaled by 2^-0.5

// ---------------- helpers ----------------
__device__ __forceinline__ uint32_t smem_u32(const void* p) {
    uint32_t a;
    asm("{ .reg .u64 t; cvta.to.shared.u64 t, %1; cvt.u32.u64 %0, t; }"
        : "=r"(a) : "l"(p));
    return a;
}

__device__ __forceinline__ void cp16(uint32_t dst, const void* src) {
    asm volatile("cp.async.cg.shared.global [%0], [%1], 16;" :: "r"(dst), "l"(src));
}

__device__ __forceinline__ void ldm_x4(uint32_t addr, uint32_t& r0, uint32_t& r1,
                                       uint32_t& r2, uint32_t& r3) {
    asm volatile("ldmatrix.sync.aligned.m8n8.x4.shared.b16 {%0,%1,%2,%3}, [%4];"
                 : "=r"(r0), "=r"(r1), "=r"(r2), "=r"(r3) : "r"(addr));
}

__device__ __forceinline__ void ldm_x4t(uint32_t addr, uint32_t& r0, uint32_t& r1,
                                        uint32_t& r2, uint32_t& r3) {
    asm volatile("ldmatrix.sync.aligned.m8n8.x4.trans.shared.b16 {%0,%1,%2,%3}, [%4];"
                 : "=r"(r0), "=r"(r1), "=r"(r2), "=r"(r3) : "r"(addr));
}

__device__ __forceinline__ void mma_fp(float* c, const uint32_t* a,
                                       uint32_t b0, uint32_t b1) {
    asm volatile(
        "mma.sync.aligned.m16n8k16.row.col.f32.f16.f16.f32 "
        "{%0,%1,%2,%3}, {%4,%5,%6,%7}, {%8,%9}, {%0,%1,%2,%3};"
        : "+f"(c[0]), "+f"(c[1]), "+f"(c[2]), "+f"(c[3])
        : "r"(a[0]), "r"(a[1]), "r"(a[2]), "r"(a[3]), "r"(b0), "r"(b1));
}

__device__ __forceinline__ void split_h(float v, uint16_t& h, uint16_t& l) {
    __half hb = __float2half_rn(v);
    __half lb = __float2half_rn(v - __half2float(hb));
    h = *(uint16_t*)&hb;
    l = *(uint16_t*)&lb;
}

// ---------------- single-fp16 HMMA GEMM (R13 config) ----------------
// C = act(A * W^T + bias)(+res); A, W single fp16.
// FM=4 -> 128x128, FM=2 -> 64x128. NST=4 stages.
// FLAGS: 1=bias, 2=gelu, 4=residual(fp32), 8=write fp16, 16=write fp32,
//        128=also write fp16 to Cb2, 256=write fp16 hi/lo (lo only c0<lo_limit)
#define GBK   32
#define GROWB 80
#define GNST  4

template<int FLAGS, bool SPLITA, int FM>
__global__ void __launch_bounds__(256, 2) gemm_f16(
    const __half* __restrict__ Ah, const __half* __restrict__ A2h,
    const __half* __restrict__ W,
    const float* __restrict__ bias, const float* __restrict__ res,
    float* __restrict__ C, uint16_t* __restrict__ Cb,
    uint16_t* __restrict__ Cph, uint16_t* __restrict__ Cpl,
    uint16_t* __restrict__ Cb2, int N, int K, int lo_limit)
{
    constexpr int BM     = FM * 32;
    constexpr int ATILEB = BM * GROWB;
    constexpr int WTILEB = 128 * GROWB;
    constexpr int STRIDE = ATILEB + WTILEB;

    extern __shared__ char smem[];
    const uint32_t sb = smem_u32(smem);
    const int tid  = threadIdx.x;
    const int wid  = tid >> 5;
    const int lane = tid & 31;
    const int wm   = wid >> 2;
    const int wn   = wid & 3;
    const int bm   = blockIdx.y * BM;
    const int bn   = blockIdx.x * 128;

    const int a_r = (FM == 4) ? (tid >> 1) : (tid >> 2);
    const int a_c = (FM == 4) ? ((tid & 1) * 16) : ((tid & 3) * 8);
    const uint32_t sA = (uint32_t)a_r * GROWB + a_c * 2;
    const size_t a_goffK = (size_t)(bm + a_r) * K + a_c;
    const size_t a_goff1 = (size_t)(bm + a_r) * 1024 + a_c;
    const int w_r = tid >> 1;
    const int w_c = (tid & 1) * 16;
    const uint32_t sW = (uint32_t)(ATILEB) + (uint32_t)w_r * GROWB + w_c * 2;
    const size_t w_goff = (size_t)(bn + w_r) * K + w_c;

    auto load_stage = [&](int s) {
        const uint32_t base = sb + (uint32_t)(s & (GNST - 1)) * STRIDE;
        const size_t ko = (size_t)s * GBK;
        const __half* pa;
        if (SPLITA) {
            pa = (ko >= 1024) ? (A2h + a_goff1 + (ko - 1024)) : (Ah + a_goff1 + ko);
        } else {
            pa = Ah + a_goffK + ko;
        }
        if (FM == 4) {
            cp16(base + sA,      pa);
            cp16(base + sA + 16, pa + 8);
        } else {
            cp16(base + sA, pa);
        }
        const __half* pw = W + w_goff + ko;
        cp16(base + sW,      pw);
        cp16(base + sW + 16, pw + 8);
        asm volatile("cp.async.commit_group;");
    };

    const int S = K / GBK;
    for (int s = 0; s < GNST - 1; s++) load_stage(s);

    float acc[FM][4][4];
#pragma unroll
    for (int i = 0; i < FM; i++)
#pragma unroll
        for (int j = 0; j < 4; j++)
#pragma unroll
            for (int k = 0; k < 4; k++) acc[i][j][k] = 0.f;

    const uint32_t aoff = (uint32_t)(wm * (FM * 16) + (lane & 15)) * GROWB
                        + (lane >> 4) * 16;
    const uint32_t boff = (uint32_t)(wn * 32 + (lane & 7) + ((lane >> 4) & 1) * 8) * GROWB
                        + ((lane >> 3) & 1) * 16 + ATILEB;

    for (int s = 0; s < S; s++) {
        asm volatile("cp.async.wait_group %0;" :: "n"(GNST - 2) : "memory");
        __syncthreads();

        const int pf = s + GNST - 1;
        if (pf < S) load_stage(pf);
        else        asm volatile("cp.async.commit_group;");

        const uint32_t base = sb + (uint32_t)(s & (GNST - 1)) * STRIDE;
        if (FM == 2) {
            uint32_t ah[2][2][4], bb[2][2][4];
#pragma unroll
            for (int k16 = 0; k16 < 2; k16++) {
#pragma unroll
                for (int fm = 0; fm < 2; fm++) {
                    const uint32_t ao = base + aoff + fm * 16 * GROWB + k16 * 32;
                    ldm_x4(ao, ah[k16][fm][0], ah[k16][fm][1],
                               ah[k16][fm][2], ah[k16][fm][3]);
                }
#pragma unroll
                for (int fnp = 0; fnp < 2; fnp++) {
                    const uint32_t bo = base + boff + fnp * 16 * GROWB + k16 * 32;
                    ldm_x4(bo, bb[k16][fnp][0], bb[k16][fnp][1],
                               bb[k16][fnp][2], bb[k16][fnp][3]);
                }
            }
#pragma unroll
            for (int k16 = 0; k16 < 2; k16++)
#pragma unroll
                for (int fm = 0; fm < 2; fm++)
#pragma unroll
                    for (int fnp = 0; fnp < 2; fnp++) {
                        mma_fp(acc[fm][fnp * 2 + 0], ah[k16][fm],
                               bb[k16][fnp][0], bb[k16][fnp][1]);
                        mma_fp(acc[fm][fnp * 2 + 1], ah[k16][fm],
                               bb[k16][fnp][2], bb[k16][fnp][3]);
                    }
        } else {
#pragma unroll
            for (int k16 = 0; k16 < 2; k16++) {
                uint32_t ah[FM][4], bb[2][4];
#pragma unroll
                for (int fm = 0; fm < FM; fm++) {
                    const uint32_t ao = base + aoff + fm * 16 * GROWB + k16 * 32;
                    ldm_x4(ao, ah[fm][0], ah[fm][1], ah[fm][2], ah[fm][3]);
                }
#pragma unroll
                for (int fnp = 0; fnp < 2; fnp++) {
                    const uint32_t bo = base + boff + fnp * 16 * GROWB + k16 * 32;
                    ldm_x4(bo, bb[fnp][0], bb[fnp][1], bb[fnp][2], bb[fnp][3]);
                }
#pragma unroll
                for (int fm = 0; fm < FM; fm++) {
#pragma unroll
                    for (int fnp = 0; fnp < 2; fnp++) {
                        mma_fp(acc[fm][fnp * 2 + 0], ah[fm], bb[fnp][0], bb[fnp][1]);
                        mma_fp(acc[fm][fnp * 2 + 1], ah[fm], bb[fnp][2], bb[fnp][3]);
                    }
                }
            }
        }
    }

    // ---- epilogue ----
#pragma unroll
    for (int fm = 0; fm < FM; fm++) {
#pragma unroll
        for (int fn = 0; fn < 4; fn++) {
            const int r0 = bm + wm * (FM * 16) + fm * 16 + (lane >> 2);
            const int c0 = bn + wn * 32 + fn * 8 + (lane & 3) * 2;
            float v[4] = { acc[fm][fn][0], acc[fm][fn][1],
                           acc[fm][fn][2], acc[fm][fn][3] };
            if (FLAGS & 1) {
                const float b0 = __ldg(bias + c0), b1 = __ldg(bias + c0 + 1);
                v[0] += b0; v[1] += b1; v[2] += b0; v[3] += b1;
            }
            if (FLAGS & 2) {
#pragma unroll
                for (int u = 0; u < 4; u++)
                    v[u] = 0.5f * v[u] * (1.f + erff(v[u] * 0.7071067811865476f));
            }
            if (FLAGS & 4) {
                const float2 ra = *(const float2*)(res + (size_t)r0 * N + c0);
                const float2 rb = *(const float2*)(res + (size_t)(r0 + 8) * N + c0);
                v[0] += ra.x; v[1] += ra.y; v[2] += rb.x; v[3] += rb.y;
            }
            if (FLAGS & 16) {
                float2 oa; oa.x = v[0]; oa.y = v[1];
                float2 ob; ob.x = v[2]; ob.y = v[3];
                *(float2*)(C + (size_t)r0 * N + c0) = oa;
                *(float2*)(C + (size_t)(r0 + 8) * N + c0) = ob;
            }
            if (FLAGS & 8) {
#pragma unroll
                for (int hf = 0; hf < 2; hf++) {
                    const int rr = r0 + hf * 8;
                    __half2 p = __floats2half2_rn(v[hf * 2 + 0], v[hf * 2 + 1]);
                    *(uint32_t*)(Cb + (size_t)rr * N + c0) = *(uint32_t*)&p;
                    if (FLAGS & 128)
                        *(uint32_t*)(Cb2 + (size_t)rr * N + c0) = *(uint32_t*)&p;
                }
            }
            if (FLAGS & 256) {
                uint16_t h0, l0, h1, l1;
                const bool store_lo = c0 < lo_limit;
#pragma unroll
                for (int hf = 0; hf < 2; hf++) {
                    const int rr = r0 + hf * 8;
                    split_h(v[hf * 2 + 0], h0, l0);
                    split_h(v[hf * 2 + 1], h1, l1);
                    *(uint32_t*)(Cph + (size_t)rr * N + c0) = (uint32_t)h0 | ((uint32_t)h1 << 16);
                    if (store_lo)
                        *(uint32_t*)(Cpl + (size_t)rr * N + c0) = (uint32_t)l0 | ((uint32_t)l1 << 16);
                }
            }
        }
    }
}

// GEMM smem sizes (NST=4)
#define GSMEM_FM4 ((128 * GROWB + 128 * GROWB) * GNST)   // 81920
#define GSMEM_FM2 ((64 * GROWB + 128 * GROWB) * GNST)    // 61440

// ---------------- fp16 flash attention, Q-tile 128 (8 warps) ----------------
// QK 3-term, PV 2-term. KV tiles shared by 2x the q-rows -> half global traffic.
#define ASTR 144
#define ATB  (64 * ASTR)          // 64-row KV tile = 9216 B
#define QTB  (128 * ASTR)         // 128-row Q tile = 18432 B
#define ATTN_SMEM (2 * QTB + 2 * 3 * ATB)   // Qh,Ql + 2 x {Kh,Kl,Vh} = 92160 B

__global__ void __launch_bounds__(256, 2) attn_hmma(
    const __half* __restrict__ qh, const __half* __restrict__ ql,
    uint16_t* __restrict__ out)
{
    extern __shared__ char smc[];
    const uint32_t sb = smem_u32(smc);
    const int b = blockIdx.z, h = blockIdx.y, q0 = blockIdx.x * 128;
    const int tid = threadIdx.x, wid = tid >> 5, lane = tid & 31;
    const float slope = -exp2f(-0.5f * (float)(h + 1));
    const size_t base = (size_t)b * 1024 * DQKV + (size_t)h * 64;

    // ---- Q load: 256 threads cover 2 tiles x 128 rows ----
    {
        const int which = tid >> 7, r = tid & 127;
        const __half* src = (which ? ql : qh) + base + (size_t)(q0 + r) * DQKV;
        const uint32_t dst = sb + which * QTB + r * ASTR;
#pragma unroll
        for (int c = 0; c < 8; c++) cp16(dst + c * 16, src + c * 8);
        asm volatile("cp.async.commit_group;");
    }

    // KV loader: warps 0-5, each 32 rows of one of {Kh, Kl, Vh}
    auto load_kv = [&](int t) {
        const uint32_t bufb = sb + 2 * QTB + (t & 1) * (3 * ATB);
        if (wid < 6) {
            const int tile = wid >> 1;
            const int r = (wid & 1) * 32 + lane;
            const __half* sp = (tile == 0) ? (qh + base + 1024)
                             : (tile == 1) ? (ql + base + 1024)
                                           : (qh + base + 2048);
            const __half* src = sp + (size_t)(t * 64 + r) * DQKV;
            const uint32_t dst = bufb + tile * ATB + r * ASTR;
#pragma unroll
            for (int c = 0; c < 8; c++) cp16(dst + c * 16, src + c * 8);
        }
        asm volatile("cp.async.commit_group;");
    };

    load_kv(0);
    asm volatile("cp.async.wait_group 0;" ::: "memory");
    __syncthreads();

    // ---- Q fragments, scaled by 0.125 (exact pow2) ----
    uint32_t qfh[4][4], qfl[4][4];
    {
        const uint32_t ao = sb + (uint32_t)(wid * 16 + (lane & 15)) * ASTR + (lane >> 4) * 16;
#pragma unroll
        for (int kk = 0; kk < 4; kk++) {
            ldm_x4(ao + kk * 32,       qfh[kk][0], qfh[kk][1], qfh[kk][2], qfh[kk][3]);
            ldm_x4(ao + QTB + kk * 32, qfl[kk][0], qfl[kk][1], qfl[kk][2], qfl[kk][3]);
        }
        const __half2 sc = __floats2half2_rn(0.125f, 0.125f);
#pragma unroll
        for (int kk = 0; kk < 4; kk++)
#pragma unroll
            for (int u = 0; u < 4; u++) {
                __half2 vh = *(__half2*)&qfh[kk][u];
                __half2 vl = *(__half2*)&qfl[kk][u];
                vh = __hmul2(vh, sc); vl = __hmul2(vl, sc);
                qfh[kk][u] = *(uint32_t*)&vh; qfl[kk][u] = *(uint32_t*)&vl;
            }
    }

    const int rA = q0 + wid * 16 + (lane >> 2);
    const int rB = rA + 8;
    const bool okA = rA < 1023, okB = rB < 1023;

    float m0 = -1e30f, m1 = -1e30f, l0s = 0.f, l1s = 0.f;
    float oacc[8][4];
#pragma unroll
    for (int j = 0; j < 8; j++)
#pragma unroll
        for (int u = 0; u < 4; u++) oacc[j][u] = 0.f;

    for (int t = 0; t < 16; t++) {
        if (t > 0) {
            asm volatile("cp.async.wait_group 0;" ::: "memory");
            __syncthreads();
        }
        if (t < 15) load_kv(t + 1);

        const uint32_t kb = sb + 2 * QTB + (t & 1) * (3 * ATB);   // Kh; Kl=+ATB
        const uint32_t vb = kb + 2 * ATB;                          // Vh

        float s[8][4];
#pragma unroll
        for (int j = 0; j < 8; j++)
#pragma unroll
            for (int u = 0; u < 4; u++) s[j][u] = 0.f;

        const uint32_t bbase = kb + (uint32_t)((lane & 7) + ((lane >> 4) & 1) * 8) * ASTR
                             + ((lane >> 3) & 1) * 16;
#pragma unroll
        for (int kk = 0; kk < 4; kk++) {
#pragma unroll
            for (int nb = 0; nb < 4; nb++) {
                uint32_t b0, b1, b2, b3, c0, c1, c2, c3;
                const uint32_t ad = bbase + nb * 16 * ASTR + kk * 32;
                ldm_x4(ad,       b0, b1, b2, b3);
                ldm_x4(ad + ATB, c0, c1, c2, c3);
                mma_fp(s[nb*2],   qfh[kk], b0, b1);
                mma_fp(s[nb*2],   qfl[kk], b0, b1);
                mma_fp(s[nb*2],   qfh[kk], c0, c1);
                mma_fp(s[nb*2+1], qfh[kk], b2, b3);
                mma_fp(s[nb*2+1], qfl[kk], b2, b3);
                mma_fp(s[nb*2+1], qfh[kk], c2, c3);
            }
        }

        float tmax0 = -1e30f, tmax1 = -1e30f;
#pragma unroll
        for (int j = 0; j < 8; j++) {
            const int kj = t * 64 + j * 8 + (lane & 3) * 2;
            const bool k0ok = kj < 1023, k1ok = kj + 1 < 1023;
            s[j][0] += (okA && k0ok) ? slope * fabsf((float)(rA - kj))     : 0.f;
            s[j][1] += (okA && k1ok) ? slope * fabsf((float)(rA - kj - 1)) : 0.f;
            s[j][2] += (okB && k0ok) ? slope * fabsf((float)(rB - kj))     : 0.f;
            s[j][3] += (okB && k1ok) ? slope * fabsf((float)(rB - kj - 1)) : 0.f;
            tmax0 = fmaxf(tmax0, fmaxf(s[j][0], s[j][1]));
            tmax1 = fmaxf(tmax1, fmaxf(s[j][2], s[j][3]));
        }
        tmax0 = fmaxf(tmax0, __shfl_xor_sync(0xffffffffu, tmax0, 1));
        tmax0 = fmaxf(tmax0, __shfl_xor_sync(0xffffffffu, tmax0, 2));
        tmax1 = fmaxf(tmax1, __shfl_xor_sync(0xffffffffu, tmax1, 1));
        tmax1 = fmaxf(tmax1, __shfl_xor_sync(0xffffffffu, tmax1, 2));

        const float mn0 = fmaxf(m0, tmax0), mn1 = fmaxf(m1, tmax1);
        const float al0 = __expf(m0 - mn0), al1 = __expf(m1 - mn1);
        m0 = mn0; m1 = mn1;

        float rs0 = 0.f, rs1 = 0.f;
#pragma unroll
        for (int j = 0; j < 8; j++) {
            s[j][0] = __expf(s[j][0] - mn0); rs0 += s[j][0];
            s[j][1] = __expf(s[j][1] - mn0); rs0 += s[j][1];
            s[j][2] = __expf(s[j][2] - mn1); rs1 += s[j][2];
            s[j][3] = __expf(s[j][3] - mn1); rs1 += s[j][3];
        }
        rs0 += __shfl_xor_sync(0xffffffffu, rs0, 1);
        rs0 += __shfl_xor_sync(0xffffffffu, rs0, 2);
        rs1 += __shfl_xor_sync(0xffffffffu, rs1, 1);
        rs1 += __shfl_xor_sync(0xffffffffu, rs1, 2);
        l0s = l0s * al0 + rs0;
        l1s = l1s * al1 + rs1;
#pragma unroll
        for (int j = 0; j < 8; j++) {
            oacc[j][0] *= al0; oacc[j][1] *= al0;
            oacc[j][2] *= al1; oacc[j][3] *= al1;
        }

        uint32_t pfh[4][4], pfl[4][4];
#pragma unroll
        for (int kk = 0; kk < 4; kk++) {
#pragma unroll
            for (int half = 0; half < 2; half++) {
                const int j = 2 * kk + half;
                uint16_t h0, l0, h1, l1, h2, l2, h3, l3;
                split_h(s[j][0], h0, l0); split_h(s[j][1], h1, l1);
                split_h(s[j][2], h2, l2); split_h(s[j][3], h3, l3);
                pfh[kk][half*2+0] = (uint32_t)h0 | ((uint32_t)h1 << 16);
                pfh[kk][half*2+1] = (uint32_t)h2 | ((uint32_t)h3 << 16);
                pfl[kk][half*2+0] = (uint32_t)l0 | ((uint32_t)l1 << 16);
                pfl[kk][half*2+1] = (uint32_t)l2 | ((uint32_t)l3 << 16);
            }
        }

        const uint32_t vbase = vb + (uint32_t)(((lane >> 3) & 1) * 8 + (lane & 7)) * ASTR
                             + (lane >> 4) * 16;
#pragma unroll
        for (int kk = 0; kk < 4; kk++) {
#pragma unroll
            for (int nb = 0; nb < 4; nb++) {
                uint32_t v0, v1, v2, v3;
                const uint32_t ad = vbase + kk * 16 * ASTR + nb * 32;
                ldm_x4t(ad, v0, v1, v2, v3);
                mma_fp(oacc[nb*2],   pfh[kk], v0, v1);
                mma_fp(oacc[nb*2],   pfl[kk], v0, v1);
                mma_fp(oacc[nb*2+1], pfh[kk], v2, v3);
                mma_fp(oacc[nb*2+1], pfl[kk], v2, v3);
            }
        }
    }

    const float inv0 = 1.f / l0s, inv1 = 1.f / l1s;
#pragma unroll
    for (int j = 0; j < 8; j++) {
        const int d0 = j * 8 + (lane & 3) * 2;
        size_t o = ((size_t)b * 1024 + rA) * DMODEL + h * 64 + d0;
        __half2 pa = __floats2half2_rn(oacc[j][0] * inv0, oacc[j][1] * inv0);
        *(uint32_t*)(out + o) = *(uint32_t*)&pa;
        o += (size_t)8 * DMODEL;
        __half2 pb = __floats2half2_rn(oacc[j][2] * inv1, oacc[j][3] * inv1);
        *(uint32_t*)(out + o) = *(uint32_t*)&pb;
    }
}

// ---------------- LayerNorm (warp-shuffle reduction) ----------------
template<bool HL>
__global__ void __launch_bounds__(256) ln_kernel2(
    const float* __restrict__ x, const float* __restrict__ g,
    float* __restrict__ y, uint16_t* __restrict__ yh)
{
    __shared__ float ws1[8], ws2[8];
    const int row = blockIdx.x;
    const int tid = threadIdx.x;
    const int wid = tid >> 5, lane = tid & 31;
    const float* xr = x + (size_t)row * DMODEL;

    float v[4];
    float s = 0.f;
#pragma unroll
    for (int u = 0; u < 4; u++) { v[u] = xr[tid + u * 256]; s += v[u]; }
#pragma unroll
    for (int o = 16; o; o >>= 1) s += __shfl_xor_sync(0xffffffffu, s, o);
    if (lane == 0) ws1[wid] = s;
    __syncthreads();
    float sum = 0.f;
#pragma unroll
    for (int w = 0; w < 8; w++) sum += ws1[w];
    const float mu = sum * (1.f / 1024.f);

    float q = 0.f;
#pragma unroll
    for (int u = 0; u < 4; u++) { const float d = v[u] - mu; q += d * d; }
#pragma unroll
    for (int o = 16; o; o >>= 1) q += __shfl_xor_sync(0xffffffffu, q, o);
    if (lane == 0) ws2[wid] = q;
    __syncthreads();
    float qs = 0.f;
#pragma unroll
    for (int w = 0; w < 8; w++) qs += ws2[w];
    const float r = rsqrtf(qs * (1.f / 1024.f) + 1e-5f);

#pragma unroll
    for (int u = 0; u < 4; u++) {
        const float val = (v[u] - mu) * r * g[tid + u * 256];
        const size_t o = (size_t)row * DMODEL + tid + u * 256;
        if (HL) {
            __half hv = __float2half_rn(val);
            yh[o] = *(uint16_t*)&hv;
        } else {
            y[o] = val;
        }
    }
}

// ---------------- fused one-shot converter ----------------
__device__ __forceinline__ uint2 h4pack(float4 v) {
    __half2 a = __floats2half2_rn(v.x, v.y);
    __half2 b = __floats2half2_rn(v.z, v.w);
    uint2 u; u.x = *(uint32_t*)&a; u.y = *(uint32_t*)&b;
    return u;
}

__global__ void __launch_bounds__(256) convert_all(
    const float4* __restrict__ x_in, float4* __restrict__ gx,
    uint2* __restrict__ xh,
    const float4* __restrict__ qw,  uint2* __restrict__ qo,
    const float4* __restrict__ aow, uint2* __restrict__ aoo,
    const float4* __restrict__ miw, uint2* __restrict__ mio,
    const float4* __restrict__ mow, uint2* __restrict__ moo,
    const float4* __restrict__ skw, uint2* __restrict__ sko)
{
    const int stride = gridDim.x * blockDim.x;
    const int g0 = blockIdx.x * blockDim.x + threadIdx.x;

    for (int i = g0; i < TOK * DMODEL / 4; i += stride) {
        float4 v = x_in[i];
        gx[i] = v;
        xh[i] = h4pack(v);
    }
    for (int i = g0; i < NL * DQKV * DMODEL / 4; i += stride) qo[i]  = h4pack(qw[i]);
    for (int i = g0; i < NL * DMODEL * DMODEL / 4; i += stride) aoo[i] = h4pack(aow[i]);
    for (int i = g0; i < NL * DFF * DMODEL / 4; i += stride) mio[i] = h4pack(miw[i]);
    for (int i = g0; i < NL * DMODEL * DFF / 4; i += stride) moo[i] = h4pack(mow[i]);
    for (int i = g0; i < 4 * DMODEL * 2 * DMODEL / 4; i += stride) {
        float4 v = skw[i];
        if (((i * 4) & 2047) >= 1024) {
            v.x *= 0.70710678118654752440f; v.y *= 0.70710678118654752440f;
            v.z *= 0.70710678118654752440f; v.w *= 0.70710678118654752440f;
        }
        sko[i] = h4pack(v);
    }
}

// ---------------- host orchestration ----------------
extern "C" void kernel_launch(void* const* d_in, const int* in_sizes, int n_in,
                              void* d_out, int out_size)
{
    (void)in_sizes; (void)n_in; (void)out_size;
    const float* x_in       = (const float*)d_in[0];
    const float* attn_w     = (const float*)d_in[1];
    const float* attn_out_w = (const float*)d_in[2];
    const float* mlp_ln_g   = (const float*)d_in[3];
    const float* mlp_in_w   = (const float*)d_in[4];
    const float* mlp_in_b   = (const float*)d_in[5];
    const float* mlp_out_w  = (const float*)d_in[6];
    const float* mlp_out_b  = (const float*)d_in[7];
    const float* skip_w     = (const float*)d_in[8];
    const float* skip_b     = (const float*)d_in[9];
    const float* out_ln_g   = (const float*)d_in[10];

    float* gx;
    cudaGetSymbolAddress((void**)&gx, g_x);

    __half *xA, *xB, *v2, *v3, *v4, *at, *ln, *ff, *qkvh, *qkvl;
    cudaGetSymbolAddress((void**)&xA, a_xA);
    cudaGetSymbolAddress((void**)&xB, a_xB);
    cudaGetSymbolAddress((void**)&v2, s_v2);
    cudaGetSymbolAddress((void**)&v3, s_v3);
    cudaGetSymbolAddress((void**)&v4, s_v4);
    cudaGetSymbolAddress((void**)&at, a_at);
    cudaGetSymbolAddress((void**)&ln, a_ln);
    cudaGetSymbolAddress((void**)&ff, a_ff);
    cudaGetSymbolAddress((void**)&qkvh, a_qkv_h);
    cudaGetSymbolAddress((void**)&qkvl, a_qkv_l);

    __half *wq, *wao, *wmi, *wmo, *wsk;
    cudaGetSymbolAddress((void**)&wq,  w_qkv);
    cudaGetSymbolAddress((void**)&wao, w_ao);
    cudaGetSymbolAddress((void**)&wmi, w_mi);
    cudaGetSymbolAddress((void**)&wmo, w_mo);
    cudaGetSymbolAddress((void**)&wsk, w_sk);

    cudaFuncSetAttribute((const void*)gemm_f16<256, false, 2>, cudaFuncAttributeMaxDynamicSharedMemorySize, GSMEM_FM2);
    cudaFuncSetAttribute((const void*)gemm_f16<28,  false, 2>, cudaFuncAttributeMaxDynamicSharedMemorySize, GSMEM_FM2);
    cudaFuncSetAttribute((const void*)gemm_f16<11,  false, 4>, cudaFuncAttributeMaxDynamicSharedMemorySize, GSMEM_FM4);
    cudaFuncSetAttribute((const void*)gemm_f16<29,  false, 2>, cudaFuncAttributeMaxDynamicSharedMemorySize, GSMEM_FM2);
    cudaFuncSetAttribute((const void*)gemm_f16<157, false, 2>, cudaFuncAttributeMaxDynamicSharedMemorySize, GSMEM_FM2);
    cudaFuncSetAttribute((const void*)gemm_f16<25,  true,  2>, cudaFuncAttributeMaxDynamicSharedMemorySize, GSMEM_FM2);
    cudaFuncSetAttribute(attn_hmma, cudaFuncAttributeMaxDynamicSharedMemorySize, ATTN_SMEM);

    convert_all<<<1184, 256>>>(
        (const float4*)x_in, (float4*)gx, (uint2*)xA,
        (const float4*)attn_w,     (uint2*)wq,
        (const float4*)attn_out_w, (uint2*)wao,
        (const float4*)mlp_in_w,   (uint2*)wmi,
        (const float4*)mlp_out_w,  (uint2*)wmo,
        (const float4*)skip_w,     (uint2*)wsk);

    __half* cur = xA;
    __half* alt = xB;

    for (int i = 0; i < NL; i++) {
        if (i >= 5) {
            __half* sv = (i == 5) ? v4 : (i == 6) ? v3 : v2;
            const int j = i - 4;
            gemm_f16<25, true, 2><<<dim3(DMODEL / 128, TOK / 64), 256, GSMEM_FM2>>>(
                cur, sv,
                wsk + (size_t)j * DMODEL * 2 * DMODEL,
                skip_b + (size_t)j * DMODEL, nullptr,
                gx, (uint16_t*)alt, nullptr, nullptr, nullptr,
                DMODEL, 2 * DMODEL, 0);
            __half* t = cur; cur = alt; alt = t;
        }
        // QKV -> fp16 hi/lo (lo only for Q,K columns < 2048)
        gemm_f16<256, false, 2><<<dim3(DQKV / 128, TOK / 64), 256, GSMEM_FM2>>>(
            cur, nullptr,
            wq + (size_t)i * DQKV * DMODEL,
            nullptr, nullptr, nullptr, nullptr,
            (uint16_t*)qkvh, (uint16_t*)qkvl, nullptr, DQKV, DMODEL, 2048);
        // attention (Q-tile 128; fp16: QK 3-term, PV 2-term) -> fp16
        attn_hmma<<<dim3(8, 16, 2), 256, ATTN_SMEM>>>(qkvh, qkvl, (uint16_t*)at);
        // attn out proj + residual -> x (fp32 + fp16)
        gemm_f16<28, false, 2><<<dim3(DMODEL / 128, TOK / 64), 256, GSMEM_FM2>>>(
            at, nullptr,
            wao + (size_t)i * DMODEL * DMODEL,
            nullptr, gx, gx, (uint16_t*)cur, nullptr, nullptr, nullptr,
            DMODEL, DMODEL, 0);
        // MLP LN -> fp16
        ln_kernel2<true><<<TOK, 256>>>(gx, mlp_ln_g + (size_t)i * DMODEL,
                                       nullptr, (uint16_t*)ln);
        // MLP in + bias + gelu -> fp16
        gemm_f16<11, false, 4><<<dim3(DFF / 128, TOK / 128), 256, GSMEM_FM4>>>(
            ln, nullptr,
            wmi + (size_t)i * DFF * DMODEL,
            mlp_in_b + (size_t)i * DFF, nullptr, nullptr,
            (uint16_t*)ff, nullptr, nullptr, nullptr, DFF, DMODEL, 0);
        // MLP out + bias + residual -> x (fp32 + fp16; layers 2/3/4 also save skip)
        if (i == 2 || i == 3 || i == 4) {
            __half* sv = (i == 2) ? v2 : (i == 3) ? v3 : v4;
            gemm_f16<157, false, 2><<<dim3(DMODEL / 128, TOK / 64), 256, GSMEM_FM2>>>(
                ff, nullptr,
                wmo + (size_t)i * DMODEL * DFF,
                mlp_out_b + (size_t)i * DMODEL, gx, gx,
                (uint16_t*)cur, nullptr, nullptr, (uint16_t*)sv,
                DMODEL, DFF, 0);
        } else {
            gemm_f16<29, false, 2><<<dim3(DMODEL / 128, TOK / 64), 256, GSMEM_FM2>>>(
                ff, nullptr,
                wmo + (size_t)i * DMODEL * DFF,
                mlp_out_b + (size_t)i * DMODEL, gx, gx,
                (uint16_t*)cur, nullptr, nullptr, nullptr, DMODEL, DFF, 0);
        }
    }

    ln_kernel2<false><<<TOK, 256>>>(gx, out_ln_g, (float*)d_out, nullptr);
}

// round 17
// speedup vs baseline: 1.2679x; 1.0446x over previous
#include <cuda_runtime.h>
#include <cuda_bf16.h>
#include <cuda_fp16.h>
#include <math.h>
#include <stdint.h>

// ---------------- problem constants ----------------
#define TOK    2048
#define DMODEL 1024
#define DQKV   3072
#define DFF    4096
#define NL     8

// ---------------- scratch (device globals, no allocs) ----------------
__device__ float g_x[TOK * DMODEL];

__device__ __half a_xA[TOK * DMODEL];
__device__ __half a_xB[TOK * DMODEL];
__device__ __half s_v2[TOK * DMODEL];
__device__ __half s_v3[TOK * DMODEL];
__device__ __half s_v4[TOK * DMODEL];
__device__ __half a_qkv_h[TOK * DQKV];
__device__ __half a_qkv_l[TOK * DQKV];   // lo stored only for Q columns
__device__ __half a_at[TOK * DMODEL];
__device__ __half a_ln[TOK * DMODEL];
__device__ __half a_ff[TOK * DFF];
__device__ __half w_qkv[NL * DQKV * DMODEL];
__device__ __half w_ao [NL * DMODEL * DMODEL];
__device__ __half w_mi [NL * DFF * DMODEL];
__device__ __half w_mo [NL * DMODEL * DFF];
__device__ __half w_sk [4 * DMODEL * 2 * DMODEL];  // cols >=1024 pre-scaled by 2^-0.5

// ---------------- helpers ----------------
__device__ __forceinline__ uint32_t smem_u32(const void* p) {
    uint32_t a;
    asm("{ .reg .u64 t; cvta.to.shared.u64 t, %1; cvt.u32.u64 %0, t; }"
        : "=r"(a) : "l"(p));
    return a;
}

__device__ __forceinline__ void cp16(uint32_t dst, const void* src) {
    asm volatile("cp.async.cg.shared.global [%0], [%1], 16;" :: "r"(dst), "l"(src));
}

__device__ __forceinline__ void ldm_x4(uint32_t addr, uint32_t& r0, uint32_t& r1,
                                       uint32_t& r2, uint32_t& r3) {
    asm volatile("ldmatrix.sync.aligned.m8n8.x4.shared.b16 {%0,%1,%2,%3}, [%4];"
                 : "=r"(r0), "=r"(r1), "=r"(r2), "=r"(r3) : "r"(addr));
}

__device__ __forceinline__ void ldm_x4t(uint32_t addr, uint32_t& r0, uint32_t& r1,
                                        uint32_t& r2, uint32_t& r3) {
    asm volatile("ldmatrix.sync.aligned.m8n8.x4.trans.shared.b16 {%0,%1,%2,%3}, [%4];"
                 : "=r"(r0), "=r"(r1), "=r"(r2), "=r"(r3) : "r"(addr));
}

__device__ __forceinline__ void mma_fp(float* c, const uint32_t* a,
                                       uint32_t b0, uint32_t b1) {
    asm volatile(
        "mma.sync.aligned.m16n8k16.row.col.f32.f16.f16.f32 "
        "{%0,%1,%2,%3}, {%4,%5,%6,%7}, {%8,%9}, {%0,%1,%2,%3};"
        : "+f"(c[0]), "+f"(c[1]), "+f"(c[2]), "+f"(c[3])
        : "r"(a[0]), "r"(a[1]), "r"(a[2]), "r"(a[3]), "r"(b0), "r"(b1));
}

__device__ __forceinline__ void split_h(float v, uint16_t& h, uint16_t& l) {
    __half hb = __float2half_rn(v);
    __half lb = __float2half_rn(v - __half2float(hb));
    h = *(uint16_t*)&hb;
    l = *(uint16_t*)&lb;
}

// ---------------- single-fp16 HMMA GEMM (R13/R16 config, unchanged) ---------
// FLAGS: 1=bias, 2=gelu, 4=residual(fp32), 8=write fp16, 16=write fp32,
//        128=also write fp16 to Cb2, 256=write fp16 hi/lo (lo only c0<lo_limit)
#define GBK   32
#define GROWB 80
#define GNST  4

template<int FLAGS, bool SPLITA, int FM>
__global__ void __launch_bounds__(256, 2) gemm_f16(
    const __half* __restrict__ Ah, const __half* __restrict__ A2h,
    const __half* __restrict__ W,
    const float* __restrict__ bias, const float* __restrict__ res,
    float* __restrict__ C, uint16_t* __restrict__ Cb,
    uint16_t* __restrict__ Cph, uint16_t* __restrict__ Cpl,
    uint16_t* __restrict__ Cb2, int N, int K, int lo_limit)
{
    constexpr int BM     = FM * 32;
    constexpr int ATILEB = BM * GROWB;
    constexpr int WTILEB = 128 * GROWB;
    constexpr int STRIDE = ATILEB + WTILEB;

    extern __shared__ char smem[];
    const uint32_t sb = smem_u32(smem);
    const int tid  = threadIdx.x;
    const int wid  = tid >> 5;
    const int lane = tid & 31;
    const int wm   = wid >> 2;
    const int wn   = wid & 3;
    const int bm   = blockIdx.y * BM;
    const int bn   = blockIdx.x * 128;

    const int a_r = (FM == 4) ? (tid >> 1) : (tid >> 2);
    const int a_c = (FM == 4) ? ((tid & 1) * 16) : ((tid & 3) * 8);
    const uint32_t sA = (uint32_t)a_r * GROWB + a_c * 2;
    const size_t a_goffK = (size_t)(bm + a_r) * K + a_c;
    const size_t a_goff1 = (size_t)(bm + a_r) * 1024 + a_c;
    const int w_r = tid >> 1;
    const int w_c = (tid & 1) * 16;
    const uint32_t sW = (uint32_t)(ATILEB) + (uint32_t)w_r * GROWB + w_c * 2;
    const size_t w_goff = (size_t)(bn + w_r) * K + w_c;

    auto load_stage = [&](int s) {
        const uint32_t base = sb + (uint32_t)(s & (GNST - 1)) * STRIDE;
        const size_t ko = (size_t)s * GBK;
        const __half* pa;
        if (SPLITA) {
            pa = (ko >= 1024) ? (A2h + a_goff1 + (ko - 1024)) : (Ah + a_goff1 + ko);
        } else {
            pa = Ah + a_goffK + ko;
        }
        if (FM == 4) {
            cp16(base + sA,      pa);
            cp16(base + sA + 16, pa + 8);
        } else {
            cp16(base + sA, pa);
        }
        const __half* pw = W + w_goff + ko;
        cp16(base + sW,      pw);
        cp16(base + sW + 16, pw + 8);
        asm volatile("cp.async.commit_group;");
    };

    const int S = K / GBK;
    for (int s = 0; s < GNST - 1; s++) load_stage(s);

    float acc[FM][4][4];
#pragma unroll
    for (int i = 0; i < FM; i++)
#pragma unroll
        for (int j = 0; j < 4; j++)
#pragma unroll
            for (int k = 0; k < 4; k++) acc[i][j][k] = 0.f;

    const uint32_t aoff = (uint32_t)(wm * (FM * 16) + (lane & 15)) * GROWB
                        + (lane >> 4) * 16;
    const uint32_t boff = (uint32_t)(wn * 32 + (lane & 7) + ((lane >> 4) & 1) * 8) * GROWB
                        + ((lane >> 3) & 1) * 16 + ATILEB;

    for (int s = 0; s < S; s++) {
        asm volatile("cp.async.wait_group %0;" :: "n"(GNST - 2) : "memory");
        __syncthreads();

        const int pf = s + GNST - 1;
        if (pf < S) load_stage(pf);
        else        asm volatile("cp.async.commit_group;");

        const uint32_t base = sb + (uint32_t)(s & (GNST - 1)) * STRIDE;
        if (FM == 2) {
            uint32_t ah[2][2][4], bb[2][2][4];
#pragma unroll
            for (int k16 = 0; k16 < 2; k16++) {
#pragma unroll
                for (int fm = 0; fm < 2; fm++) {
                    const uint32_t ao = base + aoff + fm * 16 * GROWB + k16 * 32;
                    ldm_x4(ao, ah[k16][fm][0], ah[k16][fm][1],
                               ah[k16][fm][2], ah[k16][fm][3]);
                }
#pragma unroll
                for (int fnp = 0; fnp < 2; fnp++) {
                    const uint32_t bo = base + boff + fnp * 16 * GROWB + k16 * 32;
                    ldm_x4(bo, bb[k16][fnp][0], bb[k16][fnp][1],
                               bb[k16][fnp][2], bb[k16][fnp][3]);
                }
            }
#pragma unroll
            for (int k16 = 0; k16 < 2; k16++)
#pragma unroll
                for (int fm = 0; fm < 2; fm++)
#pragma unroll
                    for (int fnp = 0; fnp < 2; fnp++) {
                        mma_fp(acc[fm][fnp * 2 + 0], ah[k16][fm],
                               bb[k16][fnp][0], bb[k16][fnp][1]);
                        mma_fp(acc[fm][fnp * 2 + 1], ah[k16][fm],
                               bb[k16][fnp][2], bb[k16][fnp][3]);
                    }
        } else {
#pragma unroll
            for (int k16 = 0; k16 < 2; k16++) {
                uint32_t ah[FM][4], bb[2][4];
#pragma unroll
                for (int fm = 0; fm < FM; fm++) {
                    const uint32_t ao = base + aoff + fm * 16 * GROWB + k16 * 32;
                    ldm_x4(ao, ah[fm][0], ah[fm][1], ah[fm][2], ah[fm][3]);
                }
#pragma unroll
                for (int fnp = 0; fnp < 2; fnp++) {
                    const uint32_t bo = base + boff + fnp * 16 * GROWB + k16 * 32;
                    ldm_x4(bo, bb[fnp][0], bb[fnp][1], bb[fnp][2], bb[fnp][3]);
                }
#pragma unroll
                for (int fm = 0; fm < FM; fm++) {
#pragma unroll
                    for (int fnp = 0; fnp < 2; fnp++) {
                        mma_fp(acc[fm][fnp * 2 + 0], ah[fm], bb[fnp][0], bb[fnp][1]);
                        mma_fp(acc[fm][fnp * 2 + 1], ah[fm], bb[fnp][2], bb[fnp][3]);
                    }
                }
            }
        }
    }

    // ---- epilogue ----
#pragma unroll
    for (int fm = 0; fm < FM; fm++) {
#pragma unroll
        for (int fn = 0; fn < 4; fn++) {
            const int r0 = bm + wm * (FM * 16) + fm * 16 + (lane >> 2);
            const int c0 = bn + wn * 32 + fn * 8 + (lane & 3) * 2;
            float v[4] = { acc[fm][fn][0], acc[fm][fn][1],
                           acc[fm][fn][2], acc[fm][fn][3] };
            if (FLAGS & 1) {
                const float b0 = __ldg(bias + c0), b1 = __ldg(bias + c0 + 1);
                v[0] += b0; v[1] += b1; v[2] += b0; v[3] += b1;
            }
            if (FLAGS & 2) {
#pragma unroll
                for (int u = 0; u < 4; u++)
                    v[u] = 0.5f * v[u] * (1.f + erff(v[u] * 0.7071067811865476f));
            }
            if (FLAGS & 4) {
                const float2 ra = *(const float2*)(res + (size_t)r0 * N + c0);
                const float2 rb = *(const float2*)(res + (size_t)(r0 + 8) * N + c0);
                v[0] += ra.x; v[1] += ra.y; v[2] += rb.x; v[3] += rb.y;
            }
            if (FLAGS & 16) {
                float2 oa; oa.x = v[0]; oa.y = v[1];
                float2 ob; ob.x = v[2]; ob.y = v[3];
                *(float2*)(C + (size_t)r0 * N + c0) = oa;
                *(float2*)(C + (size_t)(r0 + 8) * N + c0) = ob;
            }
            if (FLAGS & 8) {
#pragma unroll
                for (int hf = 0; hf < 2; hf++) {
                    const int rr = r0 + hf * 8;
                    __half2 p = __floats2half2_rn(v[hf * 2 + 0], v[hf * 2 + 1]);
                    *(uint32_t*)(Cb + (size_t)rr * N + c0) = *(uint32_t*)&p;
                    if (FLAGS & 128)
                        *(uint32_t*)(Cb2 + (size_t)rr * N + c0) = *(uint32_t*)&p;
                }
            }
            if (FLAGS & 256) {
                uint16_t h0, l0, h1, l1;
                const bool store_lo = c0 < lo_limit;
#pragma unroll
                for (int hf = 0; hf < 2; hf++) {
                    const int rr = r0 + hf * 8;
                    split_h(v[hf * 2 + 0], h0, l0);
                    split_h(v[hf * 2 + 1], h1, l1);
                    *(uint32_t*)(Cph + (size_t)rr * N + c0) = (uint32_t)h0 | ((uint32_t)h1 << 16);
                    if (store_lo)
                        *(uint32_t*)(Cpl + (size_t)rr * N + c0) = (uint32_t)l0 | ((uint32_t)l1 << 16);
                }
            }
        }
    }
}

// GEMM smem sizes (NST=4)
#define GSMEM_FM4 ((128 * GROWB + 128 * GROWB) * GNST)   // 81920
#define GSMEM_FM2 ((64 * GROWB + 128 * GROWB) * GNST)    // 61440

// ---------------- fp16 flash attention, Q-tile 128 ----------------
// QK 2-term (Qh+Ql vs single-fp16 K), PV 2-term (Ph+Pl vs single-fp16 V).
// KV buffer = {Kh, Vh} only.
#define ASTR 144
#define ATB  (64 * ASTR)          // 64-row KV tile = 9216 B
#define QTB  (128 * ASTR)         // 128-row Q tile = 18432 B
#define ATTN_SMEM (2 * QTB + 2 * 2 * ATB)   // Qh,Ql + 2 x {Kh,Vh} = 73728 B

__global__ void __launch_bounds__(256, 2) attn_hmma(
    const __half* __restrict__ qh, const __half* __restrict__ ql,
    uint16_t* __restrict__ out)
{
    extern __shared__ char smc[];
    const uint32_t sb = smem_u32(smc);
    const int b = blockIdx.z, h = blockIdx.y, q0 = blockIdx.x * 128;
    const int tid = threadIdx.x, wid = tid >> 5, lane = tid & 31;
    const float slope = -exp2f(-0.5f * (float)(h + 1));
    const size_t base = (size_t)b * 1024 * DQKV + (size_t)h * 64;

    // ---- Q load: 256 threads cover 2 tiles x 128 rows ----
    {
        const int which = tid >> 7, r = tid & 127;
        const __half* src = (which ? ql : qh) + base + (size_t)(q0 + r) * DQKV;
        const uint32_t dst = sb + which * QTB + r * ASTR;
#pragma unroll
        for (int c = 0; c < 8; c++) cp16(dst + c * 16, src + c * 8);
        asm volatile("cp.async.commit_group;");
    }

    // KV loader: warps 0-3, each 32 rows of {Kh, Vh}
    auto load_kv = [&](int t) {
        const uint32_t bufb = sb + 2 * QTB + (t & 1) * (2 * ATB);
        if (wid < 4) {
            const int tile = wid >> 1;            // 0=Kh, 1=Vh
            const int r = (wid & 1) * 32 + lane;
            const __half* sp = qh + base + (tile ? 2048 : 1024);
            const __half* src = sp + (size_t)(t * 64 + r) * DQKV;
            const uint32_t dst = bufb + tile * ATB + r * ASTR;
#pragma unroll
            for (int c = 0; c < 8; c++) cp16(dst + c * 16, src + c * 8);
        }
        asm volatile("cp.async.commit_group;");
    };

    load_kv(0);
    asm volatile("cp.async.wait_group 0;" ::: "memory");
    __syncthreads();

    // ---- Q fragments, scaled by 0.125 (exact pow2) ----
    uint32_t qfh[4][4], qfl[4][4];
    {
        const uint32_t ao = sb + (uint32_t)(wid * 16 + (lane & 15)) * ASTR + (lane >> 4) * 16;
#pragma unroll
        for (int kk = 0; kk < 4; kk++) {
            ldm_x4(ao + kk * 32,       qfh[kk][0], qfh[kk][1], qfh[kk][2], qfh[kk][3]);
            ldm_x4(ao + QTB + kk * 32, qfl[kk][0], qfl[kk][1], qfl[kk][2], qfl[kk][3]);
        }
        const __half2 sc = __floats2half2_rn(0.125f, 0.125f);
#pragma unroll
        for (int kk = 0; kk < 4; kk++)
#pragma unroll
            for (int u = 0; u < 4; u++) {
                __half2 vh = *(__half2*)&qfh[kk][u];
                __half2 vl = *(__half2*)&qfl[kk][u];
                vh = __hmul2(vh, sc); vl = __hmul2(vl, sc);
                qfh[kk][u] = *(uint32_t*)&vh; qfl[kk][u] = *(uint32_t*)&vl;
            }
    }

    const int rA = q0 + wid * 16 + (lane >> 2);
    const int rB = rA + 8;
    const bool okA = rA < 1023, okB = rB < 1023;

    float m0 = -1e30f, m1 = -1e30f, l0s = 0.f, l1s = 0.f;
    float oacc[8][4];
#pragma unroll
    for (int j = 0; j < 8; j++)
#pragma unroll
        for (int u = 0; u < 4; u++) oacc[j][u] = 0.f;

    for (int t = 0; t < 16; t++) {
        if (t > 0) {
            asm volatile("cp.async.wait_group 0;" ::: "memory");
            __syncthreads();
        }
        if (t < 15) load_kv(t + 1);

        const uint32_t kb = sb + 2 * QTB + (t & 1) * (2 * ATB);   // Kh
        const uint32_t vb = kb + ATB;                              // Vh

        // ---- scores = (Q*0.125) K^T, 2-term (Qh,Ql vs K fp16) ----
        float s[8][4];
#pragma unroll
        for (int j = 0; j < 8; j++)
#pragma unroll
            for (int u = 0; u < 4; u++) s[j][u] = 0.f;

        const uint32_t bbase = kb + (uint32_t)((lane & 7) + ((lane >> 4) & 1) * 8) * ASTR
                             + ((lane >> 3) & 1) * 16;
#pragma unroll
        for (int kk = 0; kk < 4; kk++) {
#pragma unroll
            for (int nb = 0; nb < 4; nb++) {
                uint32_t b0, b1, b2, b3;
                const uint32_t ad = bbase + nb * 16 * ASTR + kk * 32;
                ldm_x4(ad, b0, b1, b2, b3);
                mma_fp(s[nb*2],   qfh[kk], b0, b1);
                mma_fp(s[nb*2],   qfl[kk], b0, b1);
                mma_fp(s[nb*2+1], qfh[kk], b2, b3);
                mma_fp(s[nb*2+1], qfl[kk], b2, b3);
            }
        }

        // ---- alibi + online softmax (fp32) ----
        float tmax0 = -1e30f, tmax1 = -1e30f;
#pragma unroll
        for (int j = 0; j < 8; j++) {
            const int kj = t * 64 + j * 8 + (lane & 3) * 2;
            const bool k0ok = kj < 1023, k1ok = kj + 1 < 1023;
            s[j][0] += (okA && k0ok) ? slope * fabsf((float)(rA - kj))     : 0.f;
            s[j][1] += (okA && k1ok) ? slope * fabsf((float)(rA - kj - 1)) : 0.f;
            s[j][2] += (okB && k0ok) ? slope * fabsf((float)(rB - kj))     : 0.f;
            s[j][3] += (okB && k1ok) ? slope * fabsf((float)(rB - kj - 1)) : 0.f;
            tmax0 = fmaxf(tmax0, fmaxf(s[j][0], s[j][1]));
            tmax1 = fmaxf(tmax1, fmaxf(s[j][2], s[j][3]));
        }
        tmax0 = fmaxf(tmax0, __shfl_xor_sync(0xffffffffu, tmax0, 1));
        tmax0 = fmaxf(tmax0, __shfl_xor_sync(0xffffffffu, tmax0, 2));
        tmax1 = fmaxf(tmax1, __shfl_xor_sync(0xffffffffu, tmax1, 1));
        tmax1 = fmaxf(tmax1, __shfl_xor_sync(0xffffffffu, tmax1, 2));

        const float mn0 = fmaxf(m0, tmax0), mn1 = fmaxf(m1, tmax1);
        const float al0 = __expf(m0 - mn0), al1 = __expf(m1 - mn1);
        m0 = mn0; m1 = mn1;

        float rs0 = 0.f, rs1 = 0.f;
#pragma unroll
        for (int j = 0; j < 8; j++) {
            s[j][0] = __expf(s[j][0] - mn0); rs0 += s[j][0];
            s[j][1] = __expf(s[j][1] - mn0); rs0 += s[j][1];
            s[j][2] = __expf(s[j][2] - mn1); rs1 += s[j][2];
            s[j][3] = __expf(s[j][3] - mn1); rs1 += s[j][3];
        }
        rs0 += __shfl_xor_sync(0xffffffffu, rs0, 1);
        rs0 += __shfl_xor_sync(0xffffffffu, rs0, 2);
        rs1 += __shfl_xor_sync(0xffffffffu, rs1, 1);
        rs1 += __shfl_xor_sync(0xffffffffu, rs1, 2);
        l0s = l0s * al0 + rs0;
        l1s = l1s * al1 + rs1;
#pragma unroll
        for (int j = 0; j < 8; j++) {
            oacc[j][0] *= al0; oacc[j][1] *= al0;
            oacc[j][2] *= al1; oacc[j][3] *= al1;
        }

        uint32_t pfh[4][4], pfl[4][4];
#pragma unroll
        for (int kk = 0; kk < 4; kk++) {
#pragma unroll
            for (int half = 0; half < 2; half++) {
                const int j = 2 * kk + half;
                uint16_t h0, l0, h1, l1, h2, l2, h3, l3;
                split_h(s[j][0], h0, l0); split_h(s[j][1], h1, l1);
                split_h(s[j][2], h2, l2); split_h(s[j][3], h3, l3);
                pfh[kk][half*2+0] = (uint32_t)h0 | ((uint32_t)h1 << 16);
                pfh[kk][half*2+1] = (uint32_t)h2 | ((uint32_t)h3 << 16);
                pfl[kk][half*2+0] = (uint32_t)l0 | ((uint32_t)l1 << 16);
                pfl[kk][half*2+1] = (uint32_t)l2 | ((uint32_t)l3 << 16);
            }
        }

        const uint32_t vbase = vb + (uint32_t)(((lane >> 3) & 1) * 8 + (lane & 7)) * ASTR
                             + (lane >> 4) * 16;
#pragma unroll
        for (int kk = 0; kk < 4; kk++) {
#pragma unroll
            for (int nb = 0; nb < 4; nb++) {
                uint32_t v0, v1, v2, v3;
                const uint32_t ad = vbase + kk * 16 * ASTR + nb * 32;
                ldm_x4t(ad, v0, v1, v2, v3);
                mma_fp(oacc[nb*2],   pfh[kk], v0, v1);
                mma_fp(oacc[nb*2],   pfl[kk], v0, v1);
                mma_fp(oacc[nb*2+1], pfh[kk], v2, v3);
                mma_fp(oacc[nb*2+1], pfl[kk], v2, v3);
            }
        }
    }

    const float inv0 = 1.f / l0s, inv1 = 1.f / l1s;
#pragma unroll
    for (int j = 0; j < 8; j++) {
        const int d0 = j * 8 + (lane & 3) * 2;
        size_t o = ((size_t)b * 1024 + rA) * DMODEL + h * 64 + d0;
        __half2 pa = __floats2half2_rn(oacc[j][0] * inv0, oacc[j][1] * inv0);
        *(uint32_t*)(out + o) = *(uint32_t*)&pa;
        o += (size_t)8 * DMODEL;
        __half2 pb = __floats2half2_rn(oacc[j][2] * inv1, oacc[j][3] * inv1);
        *(uint32_t*)(out + o) = *(uint32_t*)&pb;
    }
}

// ---------------- LayerNorm (warp-shuffle reduction) ----------------
template<bool HL>
__global__ void __launch_bounds__(256) ln_kernel2(
    const float* __restrict__ x, const float* __restrict__ g,
    float* __restrict__ y, uint16_t* __restrict__ yh)
{
    __shared__ float ws1[8], ws2[8];
    const int row = blockIdx.x;
    const int tid = threadIdx.x;
    const int wid = tid >> 5, lane = tid & 31;
    const float* xr = x + (size_t)row * DMODEL;

    float v[4];
    float s = 0.f;
#pragma unroll
    for (int u = 0; u < 4; u++) { v[u] = xr[tid + u * 256]; s += v[u]; }
#pragma unroll
    for (int o = 16; o; o >>= 1) s += __shfl_xor_sync(0xffffffffu, s, o);
    if (lane == 0) ws1[wid] = s;
    __syncthreads();
    float sum = 0.f;
#pragma unroll
    for (int w = 0; w < 8; w++) sum += ws1[w];
    const float mu = sum * (1.f / 1024.f);

    float q = 0.f;
#pragma unroll
    for (int u = 0; u < 4; u++) { const float d = v[u] - mu; q += d * d; }
#pragma unroll
    for (int o = 16; o; o >>= 1) q += __shfl_xor_sync(0xffffffffu, q, o);
    if (lane == 0) ws2[wid] = q;
    __syncthreads();
    float qs = 0.f;
#pragma unroll
    for (int w = 0; w < 8; w++) qs += ws2[w];
    const float r = rsqrtf(qs * (1.f / 1024.f) + 1e-5f);

#pragma unroll
    for (int u = 0; u < 4; u++) {
        const float val = (v[u] - mu) * r * g[tid + u * 256];
        const size_t o = (size_t)row * DMODEL + tid + u * 256;
        if (HL) {
            __half hv = __float2half_rn(val);
            yh[o] = *(uint16_t*)&hv;
        } else {
            y[o] = val;
        }
    }
}

// ---------------- fused one-shot converter ----------------
__device__ __forceinline__ uint2 h4pack(float4 v) {
    __half2 a = __floats2half2_rn(v.x, v.y);
    __half2 b = __floats2half2_rn(v.z, v.w);
    uint2 u; u.x = *(uint32_t*)&a; u.y = *(uint32_t*)&b;
    return u;
}

__global__ void __launch_bounds__(256) convert_all(
    const float4* __restrict__ x_in, float4* __restrict__ gx,
    uint2* __restrict__ xh,
    const float4* __restrict__ qw,  uint2* __restrict__ qo,
    const float4* __restrict__ aow, uint2* __restrict__ aoo,
    const float4* __restrict__ miw, uint2* __restrict__ mio,
    const float4* __restrict__ mow, uint2* __restrict__ moo,
    const float4* __restrict__ skw, uint2* __restrict__ sko)
{
    const int stride = gridDim.x * blockDim.x;
    const int g0 = blockIdx.x * blockDim.x + threadIdx.x;

    for (int i = g0; i < TOK * DMODEL / 4; i += stride) {
        float4 v = x_in[i];
        gx[i] = v;
        xh[i] = h4pack(v);
    }
    for (int i = g0; i < NL * DQKV * DMODEL / 4; i += stride) qo[i]  = h4pack(qw[i]);
    for (int i = g0; i < NL * DMODEL * DMODEL / 4; i += stride) aoo[i] = h4pack(aow[i]);
    for (int i = g0; i < NL * DFF * DMODEL / 4; i += stride) mio[i] = h4pack(miw[i]);
    for (int i = g0; i < NL * DMODEL * DFF / 4; i += stride) moo[i] = h4pack(mow[i]);
    for (int i = g0; i < 4 * DMODEL * 2 * DMODEL / 4; i += stride) {
        float4 v = skw[i];
        if (((i * 4) & 2047) >= 1024) {
            v.x *= 0.70710678118654752440f; v.y *= 0.70710678118654752440f;
            v.z *= 0.70710678118654752440f; v.w *= 0.70710678118654752440f;
        }
        sko[i] = h4pack(v);
    }
}

// ---------------- host orchestration ----------------
extern "C" void kernel_launch(void* const* d_in, const int* in_sizes, int n_in,
                              void* d_out, int out_size)
{
    (void)in_sizes; (void)n_in; (void)out_size;
    const float* x_in       = (const float*)d_in[0];
    const float* attn_w     = (const float*)d_in[1];
    const float* attn_out_w = (const float*)d_in[2];
    const float* mlp_ln_g   = (const float*)d_in[3];
    const float* mlp_in_w   = (const float*)d_in[4];
    const float* mlp_in_b   = (const float*)d_in[5];
    const float* mlp_out_w  = (const float*)d_in[6];
    const float* mlp_out_b  = (const float*)d_in[7];
    const float* skip_w     = (const float*)d_in[8];
    const float* skip_b     = (const float*)d_in[9];
    const float* out_ln_g   = (const float*)d_in[10];

    float* gx;
    cudaGetSymbolAddress((void**)&gx, g_x);

    __half *xA, *xB, *v2, *v3, *v4, *at, *ln, *ff, *qkvh, *qkvl;
    cudaGetSymbolAddress((void**)&xA, a_xA);
    cudaGetSymbolAddress((void**)&xB, a_xB);
    cudaGetSymbolAddress((void**)&v2, s_v2);
    cudaGetSymbolAddress((void**)&v3, s_v3);
    cudaGetSymbolAddress((void**)&v4, s_v4);
    cudaGetSymbolAddress((void**)&at, a_at);
    cudaGetSymbolAddress((void**)&ln, a_ln);
    cudaGetSymbolAddress((void**)&ff, a_ff);
    cudaGetSymbolAddress((void**)&qkvh, a_qkv_h);
    cudaGetSymbolAddress((void**)&qkvl, a_qkv_l);

    __half *wq, *wao, *wmi, *wmo, *wsk;
    cudaGetSymbolAddress((void**)&wq,  w_qkv);
    cudaGetSymbolAddress((void**)&wao, w_ao);
    cudaGetSymbolAddress((void**)&wmi, w_mi);
    cudaGetSymbolAddress((void**)&wmo, w_mo);
    cudaGetSymbolAddress((void**)&wsk, w_sk);

    cudaFuncSetAttribute((const void*)gemm_f16<256, false, 2>, cudaFuncAttributeMaxDynamicSharedMemorySize, GSMEM_FM2);
    cudaFuncSetAttribute((const void*)gemm_f16<28,  false, 2>, cudaFuncAttributeMaxDynamicSharedMemorySize, GSMEM_FM2);
    cudaFuncSetAttribute((const void*)gemm_f16<11,  false, 4>, cudaFuncAttributeMaxDynamicSharedMemorySize, GSMEM_FM4);
    cudaFuncSetAttribute((const void*)gemm_f16<29,  false, 2>, cudaFuncAttributeMaxDynamicSharedMemorySize, GSMEM_FM2);
    cudaFuncSetAttribute((const void*)gemm_f16<157, false, 2>, cudaFuncAttributeMaxDynamicSharedMemorySize, GSMEM_FM2);
    cudaFuncSetAttribute((const void*)gemm_f16<25,  true,  2>, cudaFuncAttributeMaxDynamicSharedMemorySize, GSMEM_FM2);
    cudaFuncSetAttribute(attn_hmma, cudaFuncAttributeMaxDynamicSharedMemorySize, ATTN_SMEM);

    convert_all<<<1184, 256>>>(
        (const float4*)x_in, (float4*)gx, (uint2*)xA,
        (const float4*)attn_w,     (uint2*)wq,
        (const float4*)attn_out_w, (uint2*)wao,
        (const float4*)mlp_in_w,   (uint2*)wmi,
        (const float4*)mlp_out_w,  (uint2*)wmo,
        (const float4*)skip_w,     (uint2*)wsk);

    __half* cur = xA;
    __half* alt = xB;

    for (int i = 0; i < NL; i++) {
        if (i >= 5) {
            __half* sv = (i == 5) ? v4 : (i == 6) ? v3 : v2;
            const int j = i - 4;
            gemm_f16<25, true, 2><<<dim3(DMODEL / 128, TOK / 64), 256, GSMEM_FM2>>>(
                cur, sv,
                wsk + (size_t)j * DMODEL * 2 * DMODEL,
                skip_b + (size_t)j * DMODEL, nullptr,
                gx, (uint16_t*)alt, nullptr, nullptr, nullptr,
                DMODEL, 2 * DMODEL, 0);
            __half* t = cur; cur = alt; alt = t;
        }
        // QKV -> fp16 hi/lo (lo stored only for Q columns < 1024)
        gemm_f16<256, false, 2><<<dim3(DQKV / 128, TOK / 64), 256, GSMEM_FM2>>>(
            cur, nullptr,
            wq + (size_t)i * DQKV * DMODEL,
            nullptr, nullptr, nullptr, nullptr,
            (uint16_t*)qkvh, (uint16_t*)qkvl, nullptr, DQKV, DMODEL, 1024);
        // attention (Q-tile 128; QK 2-term, PV 2-term) -> fp16
        attn_hmma<<<dim3(8, 16, 2), 256, ATTN_SMEM>>>(qkvh, qkvl, (uint16_t*)at);
        // attn out proj + residual -> x (fp32 + fp16)
        gemm_f16<28, false, 2><<<dim3(DMODEL / 128, TOK / 64), 256, GSMEM_FM2>>>(
            at, nullptr,
            wao + (size_t)i * DMODEL * DMODEL,
            nullptr, gx, gx, (uint16_t*)cur, nullptr, nullptr, nullptr,
            DMODEL, DMODEL, 0);
        // MLP LN -> fp16
        ln_kernel2<true><<<TOK, 256>>>(gx, mlp_ln_g + (size_t)i * DMODEL,
                                       nullptr, (uint16_t*)ln);
        // MLP in + bias + gelu -> fp16
        gemm_f16<11, false, 4><<<dim3(DFF / 128, TOK / 128), 256, GSMEM_FM4>>>(
            ln, nullptr,
            wmi + (size_t)i * DFF * DMODEL,
            mlp_in_b + (size_t)i * DFF, nullptr, nullptr,
            (uint16_t*)ff, nullptr, nullptr, nullptr, DFF, DMODEL, 0);
        // MLP out + bias + residual -> x (fp32 + fp16; layers 2/3/4 also save skip)
        if (i == 2 || i == 3 || i == 4) {
            __half* sv = (i == 2) ? v2 : (i == 3) ? v3 : v4;
            gemm_f16<157, false, 2><<<dim3(DMODEL / 128, TOK / 64), 256, GSMEM_FM2>>>(
                ff, nullptr,
                wmo + (size_t)i * DMODEL * DFF,
                mlp_out_b + (size_t)i * DMODEL, gx, gx,
                (uint16_t*)cur, nullptr, nullptr, (uint16_t*)sv,
                DMODEL, DFF, 0);
        } else {
            gemm_f16<29, false, 2><<<dim3(DMODEL / 128, TOK / 64), 256, GSMEM_FM2>>>(
                ff, nullptr,
                wmo + (size_t)i * DMODEL * DFF,
                mlp_out_b + (size_t)i * DMODEL, gx, gx,
                (uint16_t*)cur, nullptr, nullptr, nullptr, DMODEL, DFF, 0);
        }
    }

    ln_kernel2<false><<<TOK, 256>>>(gx, out_ln_g, (float*)d_out, nullptr);
}